// round 6
// baseline (speedup 1.0000x reference)
#include <cuda_runtime.h>
#include <cuda_fp16.h>
#include <math.h>
#include <stdint.h>

// ---------------- problem constants ----------------
#define NTOK  4096            // B*L
#define LSEQ  1024
#define BATCH 4
#define DM    1024
#define DI    2048
#define DS    16
#define DTR   64
#define XPD   96              // DTR + 2*DS
#define NEXP  8
#define HEXP  1024

// ---------------- device scratch ----------------
__device__ float g_x [NTOK*DM];
__device__ float g_uz[NTOK*2*DI];
__device__ float g_u [NTOK*DI];
__device__ float g_xp[NTOK*XPD];
__device__ float g_dt[NTOK*DI];
__device__ float g_t [NTOK*DM];
__device__ float g_mask[NTOK];
__device__ float g_pooled[BATCH*DM];
__device__ int   g_eidx[NTOK];
__device__ float g_ew  [NTOK];
__device__ int   g_perm[NTOK];
__device__ int   g_cnt[NEXP], g_off[NEXP], g_fill[NEXP], g_cntb[BATCH];

// fp16 hi/lo split buffers (activations + weights)
__device__ __half g_xh[NTOK*DM],  g_xl[NTOK*DM];
__device__ __half g_uh[NTOK*DI],  g_ul[NTOK*DI];
__device__ __half g_yh[NTOK*DI],  g_yl[NTOK*DI];
__device__ __half g_hh[NTOK*HEXP],g_hl[NTOK*HEXP];
__device__ __half g_dah[NTOK*DTR],g_dal[NTOK*DTR];
__device__ __half g_wh[NEXP*HEXP*DM], g_wl[NEXP*HEXP*DM];

// ---------------- PTX helpers (base ISA only) ----------------
__device__ __forceinline__ uint32_t smem_u32(const void* p) {
    uint32_t a;
    asm("{ .reg .u64 t; cvta.to.shared.u64 t, %1; cvt.u32.u64 %0, t; }" : "=r"(a) : "l"(p));
    return a;
}
__device__ __forceinline__ void ldsm4(uint32_t* r, uint32_t addr) {
    asm volatile("ldmatrix.sync.aligned.m8n8.x4.shared.b16 {%0,%1,%2,%3}, [%4];"
        : "=r"(r[0]), "=r"(r[1]), "=r"(r[2]), "=r"(r[3]) : "r"(addr));
}
__device__ __forceinline__ void mma_f16(float* c, const uint32_t* a, uint32_t b0, uint32_t b1) {
    asm volatile("mma.sync.aligned.m16n8k16.row.col.f32.f16.f16.f32 "
        "{%0,%1,%2,%3}, {%4,%5,%6,%7}, {%8,%9}, {%0,%1,%2,%3};"
        : "+f"(c[0]), "+f"(c[1]), "+f"(c[2]), "+f"(c[3])
        : "r"(a[0]), "r"(a[1]), "r"(a[2]), "r"(a[3]), "r"(b0), "r"(b1));
}
__device__ __forceinline__ void cpa16(uint32_t saddr, const void* g, bool v) {
    int sz = v ? 16 : 0;
    asm volatile("cp.async.cg.shared.global [%0], [%1], 16, %2;"
        :: "r"(saddr), "l"(g), "r"(sz));
}
#define CP_COMMIT() asm volatile("cp.async.commit_group;" ::: "memory")
#define CP_WAIT1()  asm volatile("cp.async.wait_group 1;" ::: "memory")

// smem geometry: K-chunk 64 fp16 = 128B/row, padded to 144B (conflict-free)
// CTA tile 128(M) x 256(N)
#define ROWB   144
#define ATILE  18432              // 128 * 144
#define BTILE  36864              // 256 * 144
#define STAGEB 55296              // A + B tile
#define SM_TOT 165888             // 3 stages

// ============ fp16 mma.sync GEMM: C[M,N] = act(A @ W^T + bias) ============
// 3 K-segments: (Ah,Wh), (Ah,Wl), (Al,Wh) accumulated in fp32. Missing Al*Wl ~ 2^-22.
// mode 0: dense. mode 1: gather A rows via perm (C compact). mode 2: A compact, scatter C via perm w/ rowscale.
__global__ void __launch_bounds__(256, 1)
mma_gemm(const __half* __restrict__ Ah, const __half* __restrict__ Al, int lda,
         const __half* __restrict__ Wh, const __half* __restrict__ Wl, int ldw, size_t wz,
         float* __restrict__ C, int ldc,
         __half* __restrict__ Ch, __half* __restrict__ Cl,
         const float* __restrict__ bias, int bias_z,
         int M_fixed, const int* __restrict__ cntp, const int* __restrict__ offp,
         const int* __restrict__ perm, const float* __restrict__ rowscale,
         int mode, int N, int K, int act)
{
    int e = blockIdx.z;
    int M = cntp ? cntp[e] : M_fixed;
    int base = offp ? offp[e] : 0;
    int m0 = blockIdx.x * 128;
    if (m0 >= M) return;
    int n0 = blockIdx.y * 256;
    if (n0 >= N) return;

    extern __shared__ char smem[];
    uint32_t sb = smem_u32(smem);
    int tid = threadIdx.x;

    // ---- copy mapping: stage = 3072 x 16B chunks; thread -> 4 A rows + 8 B rows ----
    int sub = tid & 7;            // which 16B of the 128B row
    int rq = tid >> 3;            // 0..31

    int arowi[4];
    uint32_t avm = 0;
#pragma unroll
    for (int i = 0; i < 4; i++) {
        int mm = m0 + rq + 32 * i;
        bool av = mm < M;
        if (av) avm |= 1u << i;
        int ar;
        if (mode == 1)      ar = av ? perm[base + mm] : 0;
        else if (mode == 2) ar = base + (av ? mm : 0);
        else                ar = av ? mm : 0;
        arowi[i] = ar;
    }
    int wrowi[8];
    uint32_t wvm = 0;
#pragma unroll
    for (int i = 0; i < 8; i++) {
        int nr = n0 + rq + 32 * i;
        bool wv = nr < N;
        if (wv) wvm |= 1u << i;
        wrowi[i] = wv ? nr : 0;
    }
    const __half* WhE = Wh + (size_t)e * wz;
    const __half* WlE = Wl + (size_t)e * wz;

    const int NKC = K / 64;
    const int NC = 3 * NKC;

#define COPY_STAGE(c, s) do { \
        int _seg = (c) / NKC; int _k0 = ((c) - _seg * NKC) * 64; \
        const __half* _Ap = (_seg == 2) ? Al : Ah; \
        const __half* _Wp = (_seg == 1) ? WlE : WhE; \
        uint32_t _sB = sb + (uint32_t)(s) * STAGEB + rq * ROWB + sub * 16; \
        _Pragma("unroll") \
        for (int _i = 0; _i < 4; _i++) \
            cpa16(_sB + _i * (32 * ROWB), \
                  _Ap + (size_t)arowi[_i] * lda + _k0 + sub * 8, (avm >> _i) & 1); \
        _Pragma("unroll") \
        for (int _i = 0; _i < 8; _i++) \
            cpa16(_sB + _i * (32 * ROWB) + ATILE, \
                  _Wp + (size_t)wrowi[_i] * ldw + _k0 + sub * 8, (wvm >> _i) & 1); \
    } while (0)

    // ---- mma mapping: 8 warps, warp tile 64x64 (2M x 4N warp grid) ----
    int lane = tid & 31;
    int wid = tid >> 5;
    int wm = (wid & 1) * 64;      // 0 or 64
    int wn = (wid >> 1) * 64;     // 0,64,128,192

    int aRow = wm + (lane & 7) + ((lane >> 3) & 1) * 8;
    uint32_t aColB = ((lane >> 4) & 1) * 16;
    int bRow = wn + (lane & 7) + ((lane >> 4) & 1) * 8;
    uint32_t bColB = ((lane >> 3) & 1) * 16;

    float acc[4][8][4] = {};   // 4 m16-tiles x 8 n8-tiles x 4 regs

    COPY_STAGE(0, 0); CP_COMMIT();
    COPY_STAGE(1, 1); CP_COMMIT();

    for (int c = 0; c < NC; c++) {
        CP_WAIT1();
        __syncthreads();
        if (c + 2 < NC) COPY_STAGE(c + 2, (c + 2) % 3);
        CP_COMMIT();

        uint32_t Ab = sb + (uint32_t)(c % 3) * STAGEB;
        uint32_t Bb = Ab + ATILE;
#pragma unroll
        for (int st = 0; st < 4; st++) {
            uint32_t kB = st * 32;
            uint32_t a[4][4], b[4][4];
#pragma unroll
            for (int im = 0; im < 4; im++)
                ldsm4(a[im], Ab + (uint32_t)(aRow + im * 16) * ROWB + kB + aColB);
#pragma unroll
            for (int g = 0; g < 4; g++)
                ldsm4(b[g], Bb + (uint32_t)(bRow + g * 16) * ROWB + kB + bColB);
#pragma unroll
            for (int im = 0; im < 4; im++)
#pragma unroll
                for (int in = 0; in < 8; in++)
                    mma_f16(acc[im][in], a[im], b[in >> 1][(in & 1) * 2], b[in >> 1][(in & 1) * 2 + 1]);
        }
    }

    // ---- epilogue ----
    int lq = lane >> 2;
    int lr = lane & 3;
    const float* bp = bias ? (bias + (size_t)e * bias_z) : nullptr;
#pragma unroll
    for (int im = 0; im < 4; im++) {
#pragma unroll
        for (int r2 = 0; r2 < 2; r2++) {
            int m = m0 + wm + im * 16 + lq + r2 * 8;
            if (m >= M) continue;
            long crow; float scale = 1.f;
            if (mode == 2)      { crow = perm[base + m]; scale = rowscale[crow]; }
            else if (mode == 1) { crow = base + m; }
            else                { crow = m; }
#pragma unroll
            for (int in = 0; in < 8; in++) {
                int n = n0 + wn + in * 8 + lr * 2;
                if (n >= N) continue;
                float v0 = acc[im][in][r2 * 2 + 0];
                float v1 = acc[im][in][r2 * 2 + 1];
                if (bp) { v0 += bp[n]; v1 += bp[n + 1]; }
                if (act == 1) { v0 = fmaxf(v0, 0.f); v1 = fmaxf(v1, 0.f); }
                else if (act == 2) {
                    v0 = (v0 > 20.f) ? v0 : log1pf(__expf(v0));
                    v1 = (v1 > 20.f) ? v1 : log1pf(__expf(v1));
                }
                if (Ch) {
                    __half h0 = __float2half_rn(v0);
                    __half h1 = __float2half_rn(v1);
                    size_t o = (size_t)crow * ldc + n;
                    Ch[o] = h0;     Cl[o]     = __float2half_rn(v0 - __half2float(h0));
                    Ch[o + 1] = h1; Cl[o + 1] = __float2half_rn(v1 - __half2float(h1));
                } else {
                    size_t o = (size_t)crow * ldc + n;
                    C[o] = v0 * scale;
                    C[o + 1] = v1 * scale;
                }
            }
        }
    }
#undef COPY_STAGE
}

// ---------------- fp16 split helpers ----------------
__device__ __forceinline__ void split2(float v, __half& h, __half& l) {
    h = __float2half_rn(v);
    l = __float2half_rn(v - __half2float(h));
}

__global__ void wconv_k(const float* __restrict__ w, __half* __restrict__ h,
                        __half* __restrict__ l, int n) {
    int i = blockIdx.x * 256 + threadIdx.x;
    if (i >= n) return;
    split2(w[i], h[i], l[i]);
}

__global__ void dtconv_k() {  // xp[:, :DTR] -> g_dah/g_dal (compact)
    int i = blockIdx.x * 256 + threadIdx.x;   // NTOK*DTR
    int t = i >> 6, c = i & 63;
    split2(g_xp[t * XPD + c], g_dah[i], g_dal[i]);
}

// ---------------- embed ----------------
__global__ void embed_k(const int* __restrict__ tok, const float* __restrict__ emb,
                        const float* __restrict__ pos) {
    int i = blockIdx.x * blockDim.x + threadIdx.x;
    int t = i / DM, d = i % DM;
    int l = t % LSEQ;
    float v = emb[(size_t)tok[t] * DM + d] + pos[l * DM + d];
    g_x[i] = v;
    split2(v, g_xh[i], g_xl[i]);
}

// ---------------- conv + silu ----------------
__global__ void conv_silu_k(const float* __restrict__ cw, const float* __restrict__ cb) {
    int i = blockIdx.x * 256 + threadIdx.x;
    if (i >= NTOK * DI) return;
    int t = i / DI, d = i % DI;
    int b = t / LSEQ, l = t % LSEQ;
    float acc = cb[d];
#pragma unroll
    for (int k = 0; k < 4; k++) {
        int ll = l - 3 + k;
        if (ll >= 0) acc += g_uz[(size_t)(b * LSEQ + ll) * (2 * DI) + d] * cw[d * 4 + k];
    }
    float v = acc / (1.f + __expf(-acc));
    g_u[i] = v;
    split2(v, g_uh[i], g_ul[i]);
}

// ---------------- selective scan ----------------
__global__ void __launch_bounds__(128) ssm_scan_k(const float* __restrict__ A_log,
                                                  const float* __restrict__ Dp) {
    int b = blockIdx.x;
    int d = blockIdx.y * 128 + threadIdx.x;
    float A[DS];
#pragma unroll
    for (int n = 0; n < DS; n++) A[n] = -expf(A_log[d * DS + n]);
    float Dv = Dp[d];
    float h[DS];
#pragma unroll
    for (int n = 0; n < DS; n++) h[n] = 0.f;

    __shared__ float Bs[64][DS], Cs[64][DS];

    for (int c = 0; c < LSEQ / 64; c++) {
        __syncthreads();
        for (int i = threadIdx.x; i < 64 * DS; i += 128) {
            int s = i / DS, n = i % DS;
            int tok = b * LSEQ + c * 64 + s;
            Bs[s][n] = g_xp[tok * XPD + DTR + n];
            Cs[s][n] = g_xp[tok * XPD + DTR + DS + n];
        }
        __syncthreads();
        for (int s = 0; s < 64; s++) {
            int tok = b * LSEQ + c * 64 + s;
            float ut  = g_u [(size_t)tok * DI + d];
            float dtt = g_dt[(size_t)tok * DI + d];
            float du = dtt * ut;
            float yv = 0.f;
#pragma unroll
            for (int n = 0; n < DS; n++) {
                h[n] = __expf(dtt * A[n]) * h[n] + du * Bs[s][n];
                yv += h[n] * Cs[s][n];
            }
            yv += ut * Dv;
            float z = g_uz[(size_t)tok * (2 * DI) + DI + d];
            float y = yv * (z / (1.f + __expf(-z)));
            size_t o = (size_t)tok * DI + d;
            split2(y, g_yh[o], g_yl[o]);
        }
    }
}

// ---------------- x += LayerNorm(g_t), refresh hi/lo ----------------
__global__ void addln_k(const float* __restrict__ g, const float* __restrict__ bb) {
    int tok = blockIdx.x;
    const float* t = g_t + (size_t)tok * DM;
    float* x = g_x + (size_t)tok * DM;
    int tid = threadIdx.x;
    float v[4]; float s = 0.f;
#pragma unroll
    for (int i = 0; i < 4; i++) { v[i] = t[tid + i * 256]; s += v[i]; }
    __shared__ float sm[256];
    sm[tid] = s; __syncthreads();
    for (int st = 128; st > 0; st >>= 1) { if (tid < st) sm[tid] += sm[tid + st]; __syncthreads(); }
    float mean = sm[0] / DM;
    __syncthreads();
    float q = 0.f;
#pragma unroll
    for (int i = 0; i < 4; i++) { float dd = v[i] - mean; q += dd * dd; }
    sm[tid] = q; __syncthreads();
    for (int st = 128; st > 0; st >>= 1) { if (tid < st) sm[tid] += sm[tid + st]; __syncthreads(); }
    float rstd = rsqrtf(sm[0] / DM + 1e-5f);
#pragma unroll
    for (int i = 0; i < 4; i++) {
        int d = tid + i * 256;
        float nx = x[d] + (v[i] - mean) * rstd * g[d] + bb[d];
        x[d] = nx;
        split2(nx, g_xh[(size_t)tok * DM + d], g_xl[(size_t)tok * DM + d]);
    }
}

// ---------------- MoE gate ----------------
__global__ void gate_k(const float* __restrict__ gw, const float* __restrict__ gb) {
    int tok = blockIdx.x;
    const float* x = g_x + (size_t)tok * DM;
    int tid = threadIdx.x;
    float p[NEXP];
#pragma unroll
    for (int e = 0; e < NEXP; e++) p[e] = 0.f;
    for (int d = tid; d < DM; d += 256) {
        float xv = x[d];
#pragma unroll
        for (int e = 0; e < NEXP; e++) p[e] += xv * gw[e * DM + d];
    }
    __shared__ float sm[NEXP][256];
#pragma unroll
    for (int e = 0; e < NEXP; e++) sm[e][tid] = p[e];
    __syncthreads();
    for (int st = 128; st > 0; st >>= 1) {
        if (tid < st)
#pragma unroll
            for (int e = 0; e < NEXP; e++) sm[e][tid] += sm[e][tid + st];
        __syncthreads();
    }
    if (tid == 0) {
        float m = -1e30f; int bi = 0;
        float lg[NEXP];
#pragma unroll
        for (int e = 0; e < NEXP; e++) {
            lg[e] = sm[e][0] + gb[e];
            if (lg[e] > m) { m = lg[e]; bi = e; }
        }
        float ssum = 0.f;
#pragma unroll
        for (int e = 0; e < NEXP; e++) ssum += __expf(lg[e] - m);
        g_eidx[tok] = bi;
        g_ew[tok] = 1.f / ssum;
        atomicAdd(&g_cnt[bi], 1);
    }
}

__global__ void route_reset_k() { if (threadIdx.x < NEXP) { g_cnt[threadIdx.x] = 0; g_fill[threadIdx.x] = 0; } }
__global__ void route_offsets_k() {
    if (threadIdx.x == 0) { int o = 0; for (int e = 0; e < NEXP; e++) { g_off[e] = o; o += g_cnt[e]; } }
}
__global__ void route_scatter_k() {
    int tok = blockIdx.x * 256 + threadIdx.x;
    if (tok < NTOK) {
        int e = g_eidx[tok];
        int p = g_off[e] + atomicAdd(&g_fill[e], 1);
        g_perm[p] = tok;
    }
}

// ---------------- pooling + head ----------------
__global__ void cntb_reset_k() { if (threadIdx.x < BATCH) g_cntb[threadIdx.x] = 0; }

__global__ void rowmask_k() {
    int tok = blockIdx.x;
    int tid = threadIdx.x;
    float s = 0.f;
#pragma unroll
    for (int i = 0; i < 4; i++) s += g_x[(size_t)tok * DM + tid + i * 256];
    __shared__ float sm[256];
    sm[tid] = s; __syncthreads();
    for (int st = 128; st > 0; st >>= 1) { if (tid < st) sm[tid] += sm[tid + st]; __syncthreads(); }
    if (tid == 0) {
        float m = (sm[0] != 0.f) ? 1.f : 0.f;
        g_mask[tok] = m;
        if (m != 0.f) atomicAdd(&g_cntb[tok / LSEQ], 1);
    }
}

__global__ void pool_k() {
    int b = blockIdx.x;
    int d = blockIdx.y * 256 + threadIdx.x;
    float acc = 0.f;
    for (int l = 0; l < LSEQ; l++)
        acc += g_x[(size_t)(b * LSEQ + l) * DM + d] * g_mask[b * LSEQ + l];
    g_pooled[b * DM + d] = acc / fmaxf((float)g_cntb[b], 1.f);
}

__global__ void head_k(const float* __restrict__ w1, const float* __restrict__ b1,
                       const float* __restrict__ w2, const float* __restrict__ b2,
                       float* __restrict__ out) {
    int b = blockIdx.x;
    int j = threadIdx.x;
    const float* p = g_pooled + b * DM;
    float acc = b1[j];
    for (int k = 0; k < DM; k++) acc += p[k] * w1[j * DM + k];
    __shared__ float h[128];
    h[j] = fmaxf(acc, 0.f);
    __syncthreads();
    if (j < 2) {
        float o = b2[j];
        for (int k = 0; k < 128; k++) o += h[k] * w2[j * 128 + k];
        out[b * 2 + j] = o;
    }
}

// ---------------- launch ----------------
extern "C" void kernel_launch(void* const* d_in, const int* in_sizes, int n_in,
                              void* d_out, int out_size) {
    const int*   tok    = (const int*)  d_in[0];
    const float* emb    = (const float*)d_in[1];
    const float* pos    = (const float*)d_in[2];
    const float* in_w   = (const float*)d_in[3];
    const float* conv_w = (const float*)d_in[4];
    const float* conv_b = (const float*)d_in[5];
    const float* xp_w   = (const float*)d_in[6];
    const float* dt_w   = (const float*)d_in[7];
    const float* dt_b   = (const float*)d_in[8];
    const float* A_log  = (const float*)d_in[9];
    const float* D_ssm  = (const float*)d_in[10];
    const float* out_w  = (const float*)d_in[11];
    const float* ln1_g  = (const float*)d_in[12];
    const float* ln1_b  = (const float*)d_in[13];
    const float* ln2_g  = (const float*)d_in[14];
    const float* ln2_b  = (const float*)d_in[15];
    const float* gate_w = (const float*)d_in[16];
    const float* gate_b = (const float*)d_in[17];
    const float* e_w1   = (const float*)d_in[18];
    const float* e_b1   = (const float*)d_in[19];
    const float* e_w2   = (const float*)d_in[20];
    const float* e_b2   = (const float*)d_in[21];
    const float* fc1_w  = (const float*)d_in[22];
    const float* fc1_b  = (const float*)d_in[23];
    const float* fc2_w  = (const float*)d_in[24];
    const float* fc2_b  = (const float*)d_in[25];
    float* out = (float*)d_out;

    cudaFuncSetAttribute(mma_gemm, cudaFuncAttributeMaxDynamicSharedMemorySize, SM_TOT);

    float *puz, *pxp, *pdt, *pt, *pew;
    __half *pxh, *pxl, *puh, *pul, *pyh, *pyl, *phh, *phl, *pdah, *pdal, *pwh, *pwl;
    int *pcnt, *poff, *pperm;
    cudaGetSymbolAddress((void**)&puz,  g_uz);
    cudaGetSymbolAddress((void**)&pxp,  g_xp);
    cudaGetSymbolAddress((void**)&pdt,  g_dt);
    cudaGetSymbolAddress((void**)&pt,   g_t);
    cudaGetSymbolAddress((void**)&pew,  g_ew);
    cudaGetSymbolAddress((void**)&pxh,  g_xh);
    cudaGetSymbolAddress((void**)&pxl,  g_xl);
    cudaGetSymbolAddress((void**)&puh,  g_uh);
    cudaGetSymbolAddress((void**)&pul,  g_ul);
    cudaGetSymbolAddress((void**)&pyh,  g_yh);
    cudaGetSymbolAddress((void**)&pyl,  g_yl);
    cudaGetSymbolAddress((void**)&phh,  g_hh);
    cudaGetSymbolAddress((void**)&phl,  g_hl);
    cudaGetSymbolAddress((void**)&pdah, g_dah);
    cudaGetSymbolAddress((void**)&pdal, g_dal);
    cudaGetSymbolAddress((void**)&pwh,  g_wh);
    cudaGetSymbolAddress((void**)&pwl,  g_wl);
    cudaGetSymbolAddress((void**)&pcnt, g_cnt);
    cudaGetSymbolAddress((void**)&poff, g_off);
    cudaGetSymbolAddress((void**)&pperm,g_perm);

    embed_k<<<(NTOK * DM) / 256, 256>>>(tok, emb, pos);

    for (int l = 0; l < 2; l++) {
        const float* in_w_l   = in_w   + (size_t)l * (2 * DI) * DM;
        const float* conv_w_l = conv_w + (size_t)l * DI * 4;
        const float* conv_b_l = conv_b + (size_t)l * DI;
        const float* xp_w_l   = xp_w   + (size_t)l * XPD * DI;
        const float* dt_w_l   = dt_w   + (size_t)l * DI * DTR;
        const float* dt_b_l   = dt_b   + (size_t)l * DI;
        const float* A_log_l  = A_log  + (size_t)l * DI * DS;
        const float* D_l      = D_ssm  + (size_t)l * DI;
        const float* out_w_l  = out_w  + (size_t)l * DM * DI;
        const float* e_w1_l   = e_w1   + (size_t)l * NEXP * HEXP * DM;
        const float* e_b1_l   = e_b1   + (size_t)l * NEXP * HEXP;
        const float* e_w2_l   = e_w2   + (size_t)l * NEXP * DM * HEXP;
        const float* e_b2_l   = e_b2   + (size_t)l * NEXP * DM;

        // in_proj: uz = x @ in_w^T     [4096 x 4096], K=1024
        wconv_k<<<(2 * DI * DM + 255) / 256, 256>>>(in_w_l, pwh, pwl, 2 * DI * DM);
        mma_gemm<<<dim3(32, 16, 1), 256, SM_TOT>>>(
            pxh, pxl, DM, pwh, pwl, DM, 0, puz, 2 * DI, nullptr, nullptr,
            nullptr, 0, NTOK, nullptr, nullptr, nullptr, nullptr, 0, 2 * DI, DM, 0);

        conv_silu_k<<<(NTOK * DI) / 256, 256>>>(conv_w_l, conv_b_l);

        // xp = u @ xp_w^T              [4096 x 96], K=2048
        wconv_k<<<(XPD * DI + 255) / 256, 256>>>(xp_w_l, pwh, pwl, XPD * DI);
        mma_gemm<<<dim3(32, 1, 1), 256, SM_TOT>>>(
            puh, pul, DI, pwh, pwl, DI, 0, pxp, XPD, nullptr, nullptr,
            nullptr, 0, NTOK, nullptr, nullptr, nullptr, nullptr, 0, XPD, DI, 0);

        // dt = softplus(xp[:,:64] @ dt_w^T + dt_b)   [4096 x 2048], K=64
        dtconv_k<<<(NTOK * DTR) / 256, 256>>>();
        wconv_k<<<(DI * DTR + 255) / 256, 256>>>(dt_w_l, pwh, pwl, DI * DTR);
        mma_gemm<<<dim3(32, 8, 1), 256, SM_TOT>>>(
            pdah, pdal, DTR, pwh, pwl, DTR, 0, pdt, DI, nullptr, nullptr,
            dt_b_l, 0, NTOK, nullptr, nullptr, nullptr, nullptr, 0, DI, DTR, 2);

        // scan
        ssm_scan_k<<<dim3(BATCH, DI / 128), 128>>>(A_log_l, D_l);

        // out: t = y @ out_w^T         [4096 x 1024], K=2048
        wconv_k<<<(DM * DI + 255) / 256, 256>>>(out_w_l, pwh, pwl, DM * DI);
        mma_gemm<<<dim3(32, 4, 1), 256, SM_TOT>>>(
            pyh, pyl, DI, pwh, pwl, DI, 0, pt, DM, nullptr, nullptr,
            nullptr, 0, NTOK, nullptr, nullptr, nullptr, nullptr, 0, DM, DI, 0);

        addln_k<<<NTOK, 256>>>(ln1_g + (size_t)l * DM, ln1_b + (size_t)l * DM);

        // MoE routing
        route_reset_k<<<1, 32>>>();
        gate_k<<<NTOK, 256>>>(gate_w + (size_t)l * NEXP * DM, gate_b + (size_t)l * NEXP);
        route_offsets_k<<<1, 1>>>();
        route_scatter_k<<<NTOK / 256, 256>>>();

        // moe1: h = relu(gather(x) @ w1[e]^T + b1[e]) -> fp16 hi/lo
        wconv_k<<<(NEXP * HEXP * DM + 255) / 256, 256>>>(e_w1_l, pwh, pwl, NEXP * HEXP * DM);
        mma_gemm<<<dim3(32, 4, NEXP), 256, SM_TOT>>>(
            pxh, pxl, DM, pwh, pwl, DM, (size_t)HEXP * DM, nullptr, HEXP, phh, phl,
            e_b1_l, HEXP, 0, pcnt, poff, pperm, nullptr, 1, HEXP, DM, 1);

        // moe2: t = scatter(topw * (h @ w2[e]^T + b2[e]))
        wconv_k<<<(NEXP * DM * HEXP + 255) / 256, 256>>>(e_w2_l, pwh, pwl, NEXP * DM * HEXP);
        mma_gemm<<<dim3(32, 4, NEXP), 256, SM_TOT>>>(
            phh, phl, HEXP, pwh, pwl, HEXP, (size_t)DM * HEXP, pt, DM, nullptr, nullptr,
            e_b2_l, DM, 0, pcnt, poff, pperm, pew, 2, DM, HEXP, 0);

        addln_k<<<NTOK, 256>>>(ln2_g + (size_t)l * DM, ln2_b + (size_t)l * DM);
    }

    cntb_reset_k<<<1, 32>>>();
    rowmask_k<<<NTOK, 256>>>();
    pool_k<<<dim3(BATCH, DM / 256), 256>>>();
    head_k<<<BATCH, 128>>>(fc1_w, fc1_b, fc2_w, fc2_b, out);
}

// round 7
// speedup vs baseline: 1.1142x; 1.1142x over previous
#include <cuda_runtime.h>
#include <cuda_fp16.h>
#include <math.h>
#include <stdint.h>

// ---------------- problem constants ----------------
#define NTOK  4096            // B*L
#define LSEQ  1024
#define BATCH 4
#define DM    1024
#define DI    2048
#define DS    16
#define DTR   64
#define XPD   96              // DTR + 2*DS
#define NEXP  8
#define HEXP  1024

// ---------------- device scratch ----------------
__device__ float g_x [NTOK*DM];
__device__ float g_uz[NTOK*2*DI];
__device__ float g_u [NTOK*DI];
__device__ float g_xp[NTOK*XPD];
__device__ float g_dt[NTOK*DI];
__device__ float g_t [NTOK*DM];
__device__ float g_mask[NTOK];
__device__ float g_pooled[BATCH*DM];
__device__ int   g_eidx[NTOK];
__device__ float g_ew  [NTOK];
__device__ int   g_perm[NTOK];
__device__ int   g_cnt[NEXP], g_off[NEXP], g_fill[NEXP], g_cntb[BATCH];

// fp16 hi/lo split buffers (activations)
__device__ __half g_xh[NTOK*DM],  g_xl[NTOK*DM];
__device__ __half g_uh[NTOK*DI],  g_ul[NTOK*DI];
__device__ __half g_yh[NTOK*DI],  g_yl[NTOK*DI];
__device__ __half g_hh[NTOK*HEXP],g_hl[NTOK*HEXP];
__device__ __half g_dah[NTOK*DTR],g_dal[NTOK*DTR];

// per-GEMM weight split buffers, layer-indexed
__device__ __half g_inh[2][2*DI*DM],      g_inl[2][2*DI*DM];
__device__ __half g_xph[2][XPD*DI],       g_xpl[2][XPD*DI];
__device__ __half g_dwh[2][DI*DTR],       g_dwl[2][DI*DTR];
__device__ __half g_owh[2][DM*DI],        g_owl[2][DM*DI];
__device__ __half g_w1h[2][NEXP*HEXP*DM], g_w1l[2][NEXP*HEXP*DM];
__device__ __half g_w2h[2][NEXP*DM*HEXP], g_w2l[2][NEXP*DM*HEXP];

// ---------------- PTX helpers (base ISA only) ----------------
__device__ __forceinline__ uint32_t smem_u32(const void* p) {
    uint32_t a;
    asm("{ .reg .u64 t; cvta.to.shared.u64 t, %1; cvt.u32.u64 %0, t; }" : "=r"(a) : "l"(p));
    return a;
}
__device__ __forceinline__ void ldsm4(uint32_t* r, uint32_t addr) {
    asm volatile("ldmatrix.sync.aligned.m8n8.x4.shared.b16 {%0,%1,%2,%3}, [%4];"
        : "=r"(r[0]), "=r"(r[1]), "=r"(r[2]), "=r"(r[3]) : "r"(addr));
}
__device__ __forceinline__ void mma_f16(float* c, const uint32_t* a, uint32_t b0, uint32_t b1) {
    asm volatile("mma.sync.aligned.m16n8k16.row.col.f32.f16.f16.f32 "
        "{%0,%1,%2,%3}, {%4,%5,%6,%7}, {%8,%9}, {%0,%1,%2,%3};"
        : "+f"(c[0]), "+f"(c[1]), "+f"(c[2]), "+f"(c[3])
        : "r"(a[0]), "r"(a[1]), "r"(a[2]), "r"(a[3]), "r"(b0), "r"(b1));
}
__device__ __forceinline__ void cpa16(uint32_t saddr, const void* g, bool v) {
    int sz = v ? 16 : 0;
    asm volatile("cp.async.cg.shared.global [%0], [%1], 16, %2;"
        :: "r"(saddr), "l"(g), "r"(sz));
}
#define CP_COMMIT() asm volatile("cp.async.commit_group;" ::: "memory")
#define CP_WAIT1()  asm volatile("cp.async.wait_group 1;" ::: "memory")
#define CP_WAIT0()  asm volatile("cp.async.wait_group 0;" ::: "memory")

// smem geometry: K-chunk 32 fp16 = 64B/row, padded to 80B (conflict-free)
// stage = [Ah][Al][Wh][Wl], each 128 rows x 80B
#define ROWB   80
#define TILEB  10240              // 128 * 80
#define STAGEB 40960              // 4 tiles
#define SM_TOT 81920              // 2 stages

// ============ fused-split fp16 mma.sync GEMM: C = act((Ah+Al) @ (Wh+Wl)^T + bias) ============
// One K-sweep; per chunk issue Ah*Wh + Al*Wh + Ah*Wl (Al*Wl ~ 2^-22, dropped).
// mode 0: dense. mode 1: gather A rows via perm (C compact). mode 2: A compact, scatter C via perm w/ rowscale.
__global__ void __launch_bounds__(256, 2)
mma_gemm(const __half* __restrict__ Ah, const __half* __restrict__ Al, int lda,
         const __half* __restrict__ Wh, const __half* __restrict__ Wl, int ldw, size_t wz,
         float* __restrict__ C, int ldc,
         __half* __restrict__ Ch, __half* __restrict__ Cl,
         const float* __restrict__ bias, int bias_z,
         int M_fixed, const int* __restrict__ cntp, const int* __restrict__ offp,
         const int* __restrict__ perm, const float* __restrict__ rowscale,
         int mode, int N, int K, int act)
{
    int e = blockIdx.z;
    int M = cntp ? cntp[e] : M_fixed;
    int base = offp ? offp[e] : 0;
    int m0 = blockIdx.x * 128;
    if (m0 >= M) return;
    int n0 = blockIdx.y * 128;

    extern __shared__ char smem[];
    uint32_t sb = smem_u32(smem);
    int tid = threadIdx.x;

    // ---- copy mapping: per tile 512 x 16B; thread -> rows r0, r0+64, 16B slot sub ----
    int sub = tid & 3;            // which 16B of the 64B row
    int r0 = tid >> 2;            // 0..63

    size_t aoff[2]; uint32_t avm = 0;
    size_t woff[2]; uint32_t wvm = 0;
#pragma unroll
    for (int i = 0; i < 2; i++) {
        int mm = m0 + r0 + 64 * i;
        bool av = mm < M;
        if (av) avm |= 1u << i;
        int ar;
        if (mode == 1)      ar = av ? perm[base + mm] : 0;
        else if (mode == 2) ar = base + (av ? mm : 0);
        else                ar = av ? mm : 0;
        aoff[i] = (size_t)ar * lda + sub * 8;
        int nr = n0 + r0 + 64 * i;
        bool wv = nr < N;
        if (wv) wvm |= 1u << i;
        woff[i] = (size_t)(wv ? nr : 0) * ldw + sub * 8;
    }
    const __half* WhE = Wh + (size_t)e * wz;
    const __half* WlE = Wl + (size_t)e * wz;

    const int NC = K / 32;
    uint32_t srow0 = r0 * ROWB + sub * 16;
    uint32_t srow1 = (r0 + 64) * ROWB + sub * 16;

#define COPY_STAGE(c, s) do { \
        int _k0 = (c) * 32; \
        uint32_t _sB = sb + (uint32_t)(s) * STAGEB; \
        cpa16(_sB + srow0,             Ah  + aoff[0] + _k0, avm & 1); \
        cpa16(_sB + srow1,             Ah  + aoff[1] + _k0, (avm >> 1) & 1); \
        cpa16(_sB + TILEB + srow0,     Al  + aoff[0] + _k0, avm & 1); \
        cpa16(_sB + TILEB + srow1,     Al  + aoff[1] + _k0, (avm >> 1) & 1); \
        cpa16(_sB + 2*TILEB + srow0,   WhE + woff[0] + _k0, wvm & 1); \
        cpa16(_sB + 2*TILEB + srow1,   WhE + woff[1] + _k0, (wvm >> 1) & 1); \
        cpa16(_sB + 3*TILEB + srow0,   WlE + woff[0] + _k0, wvm & 1); \
        cpa16(_sB + 3*TILEB + srow1,   WlE + woff[1] + _k0, (wvm >> 1) & 1); \
    } while (0)

    // ---- mma mapping: 8 warps, warp tile 32x64 (4M x 2N) ----
    int lane = tid & 31;
    int wid = tid >> 5;
    int wm = (wid & 3) * 32;
    int wn = (wid >> 2) * 64;

    uint32_t aRB = (uint32_t)(wm + (lane & 7) + ((lane >> 3) & 1) * 8) * ROWB + ((lane >> 4) & 1) * 16;
    uint32_t bRB = (uint32_t)(wn + (lane & 7) + ((lane >> 4) & 1) * 8) * ROWB + ((lane >> 3) & 1) * 16;

    float acc[2][8][4] = {};

    COPY_STAGE(0, 0); CP_COMMIT();

    for (int c = 0; c < NC; c++) {
        if (c + 1 < NC) { COPY_STAGE(c + 1, (c + 1) & 1); CP_COMMIT(); CP_WAIT1(); }
        else            { CP_WAIT0(); }
        __syncthreads();

        uint32_t AhB = sb + (uint32_t)(c & 1) * STAGEB;
        uint32_t AlB = AhB + TILEB;
        uint32_t WhB = AhB + 2 * TILEB;
        uint32_t WlB = AhB + 3 * TILEB;
#pragma unroll
        for (int st = 0; st < 2; st++) {
            uint32_t kB = st * 32;
            uint32_t ah[2][4], al[2][4], bb[4][4];
#pragma unroll
            for (int im = 0; im < 2; im++)
                ldsm4(ah[im], AhB + (uint32_t)(im * 16) * ROWB + aRB + kB);
#pragma unroll
            for (int g = 0; g < 4; g++)
                ldsm4(bb[g], WhB + (uint32_t)(g * 16) * ROWB + bRB + kB);
#pragma unroll
            for (int im = 0; im < 2; im++)
#pragma unroll
                for (int in = 0; in < 8; in++)
                    mma_f16(acc[im][in], ah[im], bb[in >> 1][(in & 1) * 2], bb[in >> 1][(in & 1) * 2 + 1]);
#pragma unroll
            for (int im = 0; im < 2; im++)
                ldsm4(al[im], AlB + (uint32_t)(im * 16) * ROWB + aRB + kB);
#pragma unroll
            for (int im = 0; im < 2; im++)
#pragma unroll
                for (int in = 0; in < 8; in++)
                    mma_f16(acc[im][in], al[im], bb[in >> 1][(in & 1) * 2], bb[in >> 1][(in & 1) * 2 + 1]);
#pragma unroll
            for (int g = 0; g < 4; g++)
                ldsm4(bb[g], WlB + (uint32_t)(g * 16) * ROWB + bRB + kB);
#pragma unroll
            for (int im = 0; im < 2; im++)
#pragma unroll
                for (int in = 0; in < 8; in++)
                    mma_f16(acc[im][in], ah[im], bb[in >> 1][(in & 1) * 2], bb[in >> 1][(in & 1) * 2 + 1]);
        }
        __syncthreads();
    }

    // ---- epilogue ----
    int lq = lane >> 2;
    int lr = lane & 3;
    const float* bp = bias ? (bias + (size_t)e * bias_z) : nullptr;
#pragma unroll
    for (int im = 0; im < 2; im++) {
#pragma unroll
        for (int r2 = 0; r2 < 2; r2++) {
            int m = m0 + wm + im * 16 + lq + r2 * 8;
            if (m >= M) continue;
            long crow; float scale = 1.f;
            if (mode == 2)      { crow = perm[base + m]; scale = rowscale[crow]; }
            else if (mode == 1) { crow = base + m; }
            else                { crow = m; }
#pragma unroll
            for (int in = 0; in < 8; in++) {
                int n = n0 + wn + in * 8 + lr * 2;
                if (n >= N) continue;
                float v0 = acc[im][in][r2 * 2 + 0];
                float v1 = acc[im][in][r2 * 2 + 1];
                if (bp) { v0 += bp[n]; v1 += bp[n + 1]; }
                if (act == 1) { v0 = fmaxf(v0, 0.f); v1 = fmaxf(v1, 0.f); }
                else if (act == 2) {
                    v0 = (v0 > 20.f) ? v0 : log1pf(__expf(v0));
                    v1 = (v1 > 20.f) ? v1 : log1pf(__expf(v1));
                }
                if (Ch) {
                    __half h0 = __float2half_rn(v0);
                    __half h1 = __float2half_rn(v1);
                    size_t o = (size_t)crow * ldc + n;
                    Ch[o] = h0;     Cl[o]     = __float2half_rn(v0 - __half2float(h0));
                    Ch[o + 1] = h1; Cl[o + 1] = __float2half_rn(v1 - __half2float(h1));
                } else {
                    size_t o = (size_t)crow * ldc + n;
                    C[o] = v0 * scale;
                    C[o + 1] = v1 * scale;
                }
            }
        }
    }
#undef COPY_STAGE
}

// ---------------- fp16 split helpers ----------------
__device__ __forceinline__ void split2(float v, __half& h, __half& l) {
    h = __float2half_rn(v);
    l = __float2half_rn(v - __half2float(h));
}

__global__ void wconv_k(const float* __restrict__ w, __half* __restrict__ h,
                        __half* __restrict__ l, int n) {
    int i = blockIdx.x * 256 + threadIdx.x;
    if (i >= n) return;
    split2(w[i], h[i], l[i]);
}

__global__ void dtconv_k() {  // xp[:, :DTR] -> g_dah/g_dal (compact)
    int i = blockIdx.x * 256 + threadIdx.x;   // NTOK*DTR
    int t = i >> 6, c = i & 63;
    split2(g_xp[t * XPD + c], g_dah[i], g_dal[i]);
}

// ---------------- embed ----------------
__global__ void embed_k(const int* __restrict__ tok, const float* __restrict__ emb,
                        const float* __restrict__ pos) {
    int i = blockIdx.x * blockDim.x + threadIdx.x;
    int t = i / DM, d = i % DM;
    int l = t % LSEQ;
    float v = emb[(size_t)tok[t] * DM + d] + pos[l * DM + d];
    g_x[i] = v;
    split2(v, g_xh[i], g_xl[i]);
}

// ---------------- conv + silu ----------------
__global__ void conv_silu_k(const float* __restrict__ cw, const float* __restrict__ cb) {
    int i = blockIdx.x * 256 + threadIdx.x;
    if (i >= NTOK * DI) return;
    int t = i / DI, d = i % DI;
    int b = t / LSEQ, l = t % LSEQ;
    float acc = cb[d];
#pragma unroll
    for (int k = 0; k < 4; k++) {
        int ll = l - 3 + k;
        if (ll >= 0) acc += g_uz[(size_t)(b * LSEQ + ll) * (2 * DI) + d] * cw[d * 4 + k];
    }
    float v = acc / (1.f + __expf(-acc));
    g_u[i] = v;
    split2(v, g_uh[i], g_ul[i]);
}

// ---------------- selective scan ----------------
__global__ void __launch_bounds__(128) ssm_scan_k(const float* __restrict__ A_log,
                                                  const float* __restrict__ Dp) {
    int b = blockIdx.x;
    int d = blockIdx.y * 128 + threadIdx.x;
    float A[DS];
#pragma unroll
    for (int n = 0; n < DS; n++) A[n] = -expf(A_log[d * DS + n]);
    float Dv = Dp[d];
    float h[DS];
#pragma unroll
    for (int n = 0; n < DS; n++) h[n] = 0.f;

    __shared__ float Bs[64][DS], Cs[64][DS];

    for (int c = 0; c < LSEQ / 64; c++) {
        __syncthreads();
        for (int i = threadIdx.x; i < 64 * DS; i += 128) {
            int s = i / DS, n = i % DS;
            int tok = b * LSEQ + c * 64 + s;
            Bs[s][n] = g_xp[tok * XPD + DTR + n];
            Cs[s][n] = g_xp[tok * XPD + DTR + DS + n];
        }
        __syncthreads();
        for (int s = 0; s < 64; s++) {
            int tok = b * LSEQ + c * 64 + s;
            float ut  = g_u [(size_t)tok * DI + d];
            float dtt = g_dt[(size_t)tok * DI + d];
            float du = dtt * ut;
            float yv = 0.f;
#pragma unroll
            for (int n = 0; n < DS; n++) {
                h[n] = __expf(dtt * A[n]) * h[n] + du * Bs[s][n];
                yv += h[n] * Cs[s][n];
            }
            yv += ut * Dv;
            float z = g_uz[(size_t)tok * (2 * DI) + DI + d];
            float y = yv * (z / (1.f + __expf(-z)));
            size_t o = (size_t)tok * DI + d;
            split2(y, g_yh[o], g_yl[o]);
        }
    }
}

// ---------------- x += LayerNorm(g_t), refresh hi/lo ----------------
__global__ void addln_k(const float* __restrict__ g, const float* __restrict__ bb) {
    int tok = blockIdx.x;
    const float* t = g_t + (size_t)tok * DM;
    float* x = g_x + (size_t)tok * DM;
    int tid = threadIdx.x;
    float v[4]; float s = 0.f;
#pragma unroll
    for (int i = 0; i < 4; i++) { v[i] = t[tid + i * 256]; s += v[i]; }
    __shared__ float sm[256];
    sm[tid] = s; __syncthreads();
    for (int st = 128; st > 0; st >>= 1) { if (tid < st) sm[tid] += sm[tid + st]; __syncthreads(); }
    float mean = sm[0] / DM;
    __syncthreads();
    float q = 0.f;
#pragma unroll
    for (int i = 0; i < 4; i++) { float dd = v[i] - mean; q += dd * dd; }
    sm[tid] = q; __syncthreads();
    for (int st = 128; st > 0; st >>= 1) { if (tid < st) sm[tid] += sm[tid + st]; __syncthreads(); }
    float rstd = rsqrtf(sm[0] / DM + 1e-5f);
#pragma unroll
    for (int i = 0; i < 4; i++) {
        int d = tid + i * 256;
        float nx = x[d] + (v[i] - mean) * rstd * g[d] + bb[d];
        x[d] = nx;
        split2(nx, g_xh[(size_t)tok * DM + d], g_xl[(size_t)tok * DM + d]);
    }
}

// ---------------- MoE gate ----------------
__global__ void gate_k(const float* __restrict__ gw, const float* __restrict__ gb) {
    int tok = blockIdx.x;
    const float* x = g_x + (size_t)tok * DM;
    int tid = threadIdx.x;
    float p[NEXP];
#pragma unroll
    for (int e = 0; e < NEXP; e++) p[e] = 0.f;
    for (int d = tid; d < DM; d += 256) {
        float xv = x[d];
#pragma unroll
        for (int e = 0; e < NEXP; e++) p[e] += xv * gw[e * DM + d];
    }
    __shared__ float sm[NEXP][256];
#pragma unroll
    for (int e = 0; e < NEXP; e++) sm[e][tid] = p[e];
    __syncthreads();
    for (int st = 128; st > 0; st >>= 1) {
        if (tid < st)
#pragma unroll
            for (int e = 0; e < NEXP; e++) sm[e][tid] += sm[e][tid + st];
        __syncthreads();
    }
    if (tid == 0) {
        float m = -1e30f; int bi = 0;
        float lg[NEXP];
#pragma unroll
        for (int e = 0; e < NEXP; e++) {
            lg[e] = sm[e][0] + gb[e];
            if (lg[e] > m) { m = lg[e]; bi = e; }
        }
        float ssum = 0.f;
#pragma unroll
        for (int e = 0; e < NEXP; e++) ssum += __expf(lg[e] - m);
        g_eidx[tok] = bi;
        g_ew[tok] = 1.f / ssum;
        atomicAdd(&g_cnt[bi], 1);
    }
}

__global__ void route_reset_k() { if (threadIdx.x < NEXP) { g_cnt[threadIdx.x] = 0; g_fill[threadIdx.x] = 0; } }
__global__ void route_offsets_k() {
    if (threadIdx.x == 0) { int o = 0; for (int e = 0; e < NEXP; e++) { g_off[e] = o; o += g_cnt[e]; } }
}
__global__ void route_scatter_k() {
    int tok = blockIdx.x * 256 + threadIdx.x;
    if (tok < NTOK) {
        int e = g_eidx[tok];
        int p = g_off[e] + atomicAdd(&g_fill[e], 1);
        g_perm[p] = tok;
    }
}

// ---------------- pooling + head ----------------
__global__ void cntb_reset_k() { if (threadIdx.x < BATCH) g_cntb[threadIdx.x] = 0; }

__global__ void rowmask_k() {
    int tok = blockIdx.x;
    int tid = threadIdx.x;
    float s = 0.f;
#pragma unroll
    for (int i = 0; i < 4; i++) s += g_x[(size_t)tok * DM + tid + i * 256];
    __shared__ float sm[256];
    sm[tid] = s; __syncthreads();
    for (int st = 128; st > 0; st >>= 1) { if (tid < st) sm[tid] += sm[tid + st]; __syncthreads(); }
    if (tid == 0) {
        float m = (sm[0] != 0.f) ? 1.f : 0.f;
        g_mask[tok] = m;
        if (m != 0.f) atomicAdd(&g_cntb[tok / LSEQ], 1);
    }
}

__global__ void pool_k() {
    int b = blockIdx.x;
    int d = blockIdx.y * 256 + threadIdx.x;
    float acc = 0.f;
    for (int l = 0; l < LSEQ; l++)
        acc += g_x[(size_t)(b * LSEQ + l) * DM + d] * g_mask[b * LSEQ + l];
    g_pooled[b * DM + d] = acc / fmaxf((float)g_cntb[b], 1.f);
}

__global__ void head_k(const float* __restrict__ w1, const float* __restrict__ b1,
                       const float* __restrict__ w2, const float* __restrict__ b2,
                       float* __restrict__ out) {
    int b = blockIdx.x;
    int j = threadIdx.x;
    const float* p = g_pooled + b * DM;
    float acc = b1[j];
    for (int k = 0; k < DM; k++) acc += p[k] * w1[j * DM + k];
    __shared__ float h[128];
    h[j] = fmaxf(acc, 0.f);
    __syncthreads();
    if (j < 2) {
        float o = b2[j];
        for (int k = 0; k < 128; k++) o += h[k] * w2[j * 128 + k];
        out[b * 2 + j] = o;
    }
}

// ---------------- launch ----------------
extern "C" void kernel_launch(void* const* d_in, const int* in_sizes, int n_in,
                              void* d_out, int out_size) {
    const int*   tok    = (const int*)  d_in[0];
    const float* emb    = (const float*)d_in[1];
    const float* pos    = (const float*)d_in[2];
    const float* in_w   = (const float*)d_in[3];
    const float* conv_w = (const float*)d_in[4];
    const float* conv_b = (const float*)d_in[5];
    const float* xp_w   = (const float*)d_in[6];
    const float* dt_w   = (const float*)d_in[7];
    const float* dt_b   = (const float*)d_in[8];
    const float* A_log  = (const float*)d_in[9];
    const float* D_ssm  = (const float*)d_in[10];
    const float* out_w  = (const float*)d_in[11];
    const float* ln1_g  = (const float*)d_in[12];
    const float* ln1_b  = (const float*)d_in[13];
    const float* ln2_g  = (const float*)d_in[14];
    const float* ln2_b  = (const float*)d_in[15];
    const float* gate_w = (const float*)d_in[16];
    const float* gate_b = (const float*)d_in[17];
    const float* e_w1   = (const float*)d_in[18];
    const float* e_b1   = (const float*)d_in[19];
    const float* e_w2   = (const float*)d_in[20];
    const float* e_b2   = (const float*)d_in[21];
    const float* fc1_w  = (const float*)d_in[22];
    const float* fc1_b  = (const float*)d_in[23];
    const float* fc2_w  = (const float*)d_in[24];
    const float* fc2_b  = (const float*)d_in[25];
    float* out = (float*)d_out;

    cudaFuncSetAttribute(mma_gemm, cudaFuncAttributeMaxDynamicSharedMemorySize, SM_TOT);

    float *puz, *pxp, *pdt, *pt, *pew;
    __half *pxh, *pxl, *puh, *pul, *pyh, *pyl, *phh, *phl, *pdah, *pdal;
    __half *pinh, *pinl, *pxph, *pxpl, *pdwh, *pdwl, *powh, *powl, *pw1h, *pw1l, *pw2h, *pw2l;
    int *pcnt, *poff, *pperm;
    cudaGetSymbolAddress((void**)&puz,  g_uz);
    cudaGetSymbolAddress((void**)&pxp,  g_xp);
    cudaGetSymbolAddress((void**)&pdt,  g_dt);
    cudaGetSymbolAddress((void**)&pt,   g_t);
    cudaGetSymbolAddress((void**)&pew,  g_ew);
    cudaGetSymbolAddress((void**)&pxh,  g_xh);
    cudaGetSymbolAddress((void**)&pxl,  g_xl);
    cudaGetSymbolAddress((void**)&puh,  g_uh);
    cudaGetSymbolAddress((void**)&pul,  g_ul);
    cudaGetSymbolAddress((void**)&pyh,  g_yh);
    cudaGetSymbolAddress((void**)&pyl,  g_yl);
    cudaGetSymbolAddress((void**)&phh,  g_hh);
    cudaGetSymbolAddress((void**)&phl,  g_hl);
    cudaGetSymbolAddress((void**)&pdah, g_dah);
    cudaGetSymbolAddress((void**)&pdal, g_dal);
    cudaGetSymbolAddress((void**)&pinh, g_inh);
    cudaGetSymbolAddress((void**)&pinl, g_inl);
    cudaGetSymbolAddress((void**)&pxph, g_xph);
    cudaGetSymbolAddress((void**)&pxpl, g_xpl);
    cudaGetSymbolAddress((void**)&pdwh, g_dwh);
    cudaGetSymbolAddress((void**)&pdwl, g_dwl);
    cudaGetSymbolAddress((void**)&powh, g_owh);
    cudaGetSymbolAddress((void**)&powl, g_owl);
    cudaGetSymbolAddress((void**)&pw1h, g_w1h);
    cudaGetSymbolAddress((void**)&pw1l, g_w1l);
    cudaGetSymbolAddress((void**)&pw2h, g_w2h);
    cudaGetSymbolAddress((void**)&pw2l, g_w2l);
    cudaGetSymbolAddress((void**)&pcnt, g_cnt);
    cudaGetSymbolAddress((void**)&poff, g_off);
    cudaGetSymbolAddress((void**)&pperm,g_perm);

    const size_t SZ_IN = (size_t)2 * DI * DM, SZ_XP = (size_t)XPD * DI,
                 SZ_DW = (size_t)DI * DTR,    SZ_OW = (size_t)DM * DI,
                 SZ_W1 = (size_t)NEXP * HEXP * DM, SZ_W2 = (size_t)NEXP * DM * HEXP;

    embed_k<<<(NTOK * DM) / 256, 256>>>(tok, emb, pos);

    for (int l = 0; l < 2; l++) {
        __half *inh = pinh + l * SZ_IN, *inl = pinl + l * SZ_IN;
        __half *xph = pxph + l * SZ_XP, *xpl = pxpl + l * SZ_XP;
        __half *dwh = pdwh + l * SZ_DW, *dwl = pdwl + l * SZ_DW;
        __half *owh = powh + l * SZ_OW, *owl = powl + l * SZ_OW;
        __half *w1h = pw1h + l * SZ_W1, *w1l = pw1l + l * SZ_W1;
        __half *w2h = pw2h + l * SZ_W2, *w2l = pw2l + l * SZ_W2;

        // conversions ordered so launches #4/#6 (layer 0) are the big mma_gemms
        wconv_k<<<(int)((SZ_IN + 255) / 256), 256>>>(in_w + l * SZ_IN, inh, inl, (int)SZ_IN);
        wconv_k<<<(int)((SZ_XP + 255) / 256), 256>>>(xp_w + l * SZ_XP, xph, xpl, (int)SZ_XP);

        // in_proj: uz = x @ in_w^T     [4096 x 4096], K=1024
        mma_gemm<<<dim3(32, 32, 1), 256, SM_TOT>>>(
            pxh, pxl, DM, inh, inl, DM, 0, puz, 2 * DI, nullptr, nullptr,
            nullptr, 0, NTOK, nullptr, nullptr, nullptr, nullptr, 0, 2 * DI, DM, 0);

        conv_silu_k<<<(NTOK * DI) / 256, 256>>>(conv_w + (size_t)l * DI * 4, conv_b + (size_t)l * DI);

        // xp = u @ xp_w^T              [4096 x 96], K=2048
        mma_gemm<<<dim3(32, 1, 1), 256, SM_TOT>>>(
            puh, pul, DI, xph, xpl, DI, 0, pxp, XPD, nullptr, nullptr,
            nullptr, 0, NTOK, nullptr, nullptr, nullptr, nullptr, 0, XPD, DI, 0);

        // dt = softplus(xp[:,:64] @ dt_w^T + dt_b)   [4096 x 2048], K=64
        dtconv_k<<<(NTOK * DTR) / 256, 256>>>();
        wconv_k<<<(int)((SZ_DW + 255) / 256), 256>>>(dt_w + l * SZ_DW, dwh, dwl, (int)SZ_DW);
        mma_gemm<<<dim3(32, 16, 1), 256, SM_TOT>>>(
            pdah, pdal, DTR, dwh, dwl, DTR, 0, pdt, DI, nullptr, nullptr,
            dt_b + (size_t)l * DI, 0, NTOK, nullptr, nullptr, nullptr, nullptr, 0, DI, DTR, 2);

        // scan
        ssm_scan_k<<<dim3(BATCH, DI / 128), 128>>>(A_log + (size_t)l * DI * DS, D_ssm + (size_t)l * DI);

        // out: t = y @ out_w^T         [4096 x 1024], K=2048
        wconv_k<<<(int)((SZ_OW + 255) / 256), 256>>>(out_w + l * SZ_OW, owh, owl, (int)SZ_OW);
        mma_gemm<<<dim3(32, 8, 1), 256, SM_TOT>>>(
            pyh, pyl, DI, owh, owl, DI, 0, pt, DM, nullptr, nullptr,
            nullptr, 0, NTOK, nullptr, nullptr, nullptr, nullptr, 0, DM, DI, 0);

        addln_k<<<NTOK, 256>>>(ln1_g + (size_t)l * DM, ln1_b + (size_t)l * DM);

        // MoE routing
        route_reset_k<<<1, 32>>>();
        gate_k<<<NTOK, 256>>>(gate_w + (size_t)l * NEXP * DM, gate_b + (size_t)l * NEXP);
        route_offsets_k<<<1, 1>>>();
        route_scatter_k<<<NTOK / 256, 256>>>();

        // moe1: h = relu(gather(x) @ w1[e]^T + b1[e]) -> fp16 hi/lo
        wconv_k<<<(int)((SZ_W1 + 255) / 256), 256>>>(e_w1 + l * SZ_W1, w1h, w1l, (int)SZ_W1);
        mma_gemm<<<dim3(32, 8, NEXP), 256, SM_TOT>>>(
            pxh, pxl, DM, w1h, w1l, DM, (size_t)HEXP * DM, nullptr, HEXP, phh, phl,
            e_b1 + (size_t)l * NEXP * HEXP, HEXP, 0, pcnt, poff, pperm, nullptr, 1, HEXP, DM, 1);

        // moe2: t = scatter(topw * (h @ w2[e]^T + b2[e]))
        wconv_k<<<(int)((SZ_W2 + 255) / 256), 256>>>(e_w2 + l * SZ_W2, w2h, w2l, (int)SZ_W2);
        mma_gemm<<<dim3(32, 8, NEXP), 256, SM_TOT>>>(
            phh, phl, HEXP, w2h, w2l, HEXP, (size_t)DM * HEXP, pt, DM, nullptr, nullptr,
            e_b2 + (size_t)l * NEXP * DM, DM, 0, pcnt, poff, pperm, pew, 2, DM, HEXP, 0);

        addln_k<<<NTOK, 256>>>(ln2_g + (size_t)l * DM, ln2_b + (size_t)l * DM);
    }

    cntb_reset_k<<<1, 32>>>();
    rowmask_k<<<NTOK, 256>>>();
    pool_k<<<dim3(BATCH, DM / 256), 256>>>();
    head_k<<<BATCH, 128>>>(fc1_w, fc1_b, fc2_w, fc2_b, out);
}

// round 8
// speedup vs baseline: 1.9121x; 1.7161x over previous
#include <cuda_runtime.h>
#include <cuda_fp16.h>
#include <math.h>
#include <stdint.h>

// ---------------- problem constants ----------------
#define NTOK  4096            // B*L
#define LSEQ  1024
#define BATCH 4
#define DM    1024
#define DI    2048
#define DS    16
#define DTR   64
#define XPD   96              // DTR + 2*DS
#define NEXP  8
#define HEXP  1024
#define KSPL  8               // split-K factor for xp gemm

// ---------------- device scratch ----------------
__device__ float g_x [NTOK*DM];
__device__ float g_uz[NTOK*2*DI];
__device__ float g_u [NTOK*DI];
__device__ float g_xp[NTOK*XPD];
__device__ float g_xps[KSPL*NTOK*XPD];
__device__ float g_dt[NTOK*DI];
__device__ float g_t [NTOK*DM];
__device__ float g_mask[NTOK];
__device__ float g_pooled[BATCH*DM];
__device__ int   g_eidx[NTOK];
__device__ float g_ew  [NTOK];
__device__ int   g_perm[NTOK];
__device__ int   g_cnt[NEXP], g_off[NEXP], g_fill[NEXP], g_cntb[BATCH];

// fp16 hi/lo split buffers (activations only)
__device__ __half g_xh[NTOK*DM],  g_xl[NTOK*DM];
__device__ __half g_uh[NTOK*DI],  g_ul[NTOK*DI];
__device__ __half g_yh[NTOK*DI],  g_yl[NTOK*DI];
__device__ __half g_hh[NTOK*HEXP],g_hl[NTOK*HEXP];
__device__ __half g_dah[NTOK*DTR],g_dal[NTOK*DTR];

// ---------------- PTX helpers (base ISA only) ----------------
__device__ __forceinline__ uint32_t smem_u32(const void* p) {
    uint32_t a;
    asm("{ .reg .u64 t; cvta.to.shared.u64 t, %1; cvt.u32.u64 %0, t; }" : "=r"(a) : "l"(p));
    return a;
}
__device__ __forceinline__ void ldsm4(uint32_t* r, uint32_t addr) {
    asm volatile("ldmatrix.sync.aligned.m8n8.x4.shared.b16 {%0,%1,%2,%3}, [%4];"
        : "=r"(r[0]), "=r"(r[1]), "=r"(r[2]), "=r"(r[3]) : "r"(addr));
}
__device__ __forceinline__ void mma_f16(float* c, const uint32_t* a, uint32_t b0, uint32_t b1) {
    asm volatile("mma.sync.aligned.m16n8k16.row.col.f32.f16.f16.f32 "
        "{%0,%1,%2,%3}, {%4,%5,%6,%7}, {%8,%9}, {%0,%1,%2,%3};"
        : "+f"(c[0]), "+f"(c[1]), "+f"(c[2]), "+f"(c[3])
        : "r"(a[0]), "r"(a[1]), "r"(a[2]), "r"(a[3]), "r"(b0), "r"(b1));
}
__device__ __forceinline__ void cpa16(uint32_t saddr, const void* g, bool v) {
    int sz = v ? 16 : 0;
    asm volatile("cp.async.cg.shared.global [%0], [%1], 16, %2;"
        :: "r"(saddr), "l"(g), "r"(sz));
}
__device__ __forceinline__ void cpa16f(uint32_t saddr, const void* g) {
    asm volatile("cp.async.cg.shared.global [%0], [%1], 16;"
        :: "r"(saddr), "l"(g));
}
#define CP_COMMIT() asm volatile("cp.async.commit_group;" ::: "memory")
#define CP_WAIT1()  asm volatile("cp.async.wait_group 1;" ::: "memory")
#define CP_WAIT0()  asm volatile("cp.async.wait_group 0;" ::: "memory")

// smem geometry: K-chunk 32 fp16 = 64B/row, padded to 80B
// stage = [Ah][Al][Wh][Wl], each 128 rows x 80B
#define ROWB   80
#define TILEB  10240              // 128 * 80
#define STAGEB 40960              // 4 tiles
#define SM_TOT 81920              // 2 stages

// ============ fused-split fp16 mma.sync GEMM: C = act(A @ W^T + bias) ============
// A pre-split halves (cp.async); W fp32 converted in-kernel (LDG->split->STS).
// Per chunk: Ah*Wh + Al*Wh + Ah*Wl (Al*Wl ~ 2^-22 dropped).
// mode 0: dense. mode 1: gather A rows via perm. mode 2: A compact, scatter C w/ rowscale.
// z-dim: expert (cntp) or K-split (az/wz/czs offsets).
__global__ void __launch_bounds__(256, 2)
mma_gemm(const __half* __restrict__ Ah, const __half* __restrict__ Al, int lda, int az,
         const float* __restrict__ W32, int ldw, size_t wz,
         float* __restrict__ C, int ldc, size_t czs,
         __half* __restrict__ Ch, __half* __restrict__ Cl,
         const float* __restrict__ bias, int bias_z,
         int M_fixed, const int* __restrict__ cntp, const int* __restrict__ offp,
         const int* __restrict__ perm, const float* __restrict__ rowscale,
         int mode, int N, int K, int act)
{
    int e = blockIdx.z;
    int M = cntp ? cntp[e] : M_fixed;
    int base = offp ? offp[e] : 0;
    int m0 = blockIdx.x * 128;
    if (m0 >= M) return;
    int n0 = blockIdx.y * 128;

    extern __shared__ char smem[];
    uint32_t sb = smem_u32(smem);
    int tid = threadIdx.x;

    // ---- A copy mapping: per tile 512 x 16B; thread -> rows r0, r0+64, slot sub ----
    int sub = tid & 3;
    int r0 = tid >> 2;
    size_t aoff[2]; uint32_t avm = 0;
#pragma unroll
    for (int i = 0; i < 2; i++) {
        int mm = m0 + r0 + 64 * i;
        bool av = mm < M;
        if (av) avm |= 1u << i;
        int ar;
        if (mode == 1)      ar = av ? perm[base + mm] : 0;
        else if (mode == 2) ar = base + (av ? mm : 0);
        else                ar = av ? mm : 0;
        aoff[i] = (size_t)ar * lda + sub * 8 + (size_t)e * az;
    }
    uint32_t srow0 = r0 * ROWB + sub * 16;
    uint32_t srow1 = (r0 + 64) * ROWB + sub * 16;

    // ---- W mapping: thread -> row tid>>1, half (tid&1)*16 floats ----
    int wrow_l = tid >> 1;
    int wn = n0 + wrow_l;
    if (wn >= N) wn = 0;
    int khalf = (tid & 1) * 16;
    const float* WE = W32 + (size_t)e * wz + (size_t)wn * ldw + khalf;
    uint32_t wsts = (uint32_t)wrow_l * ROWB + (tid & 1) * 32;

    const int NC = K / 32;
    float4 wr[4];

#define COPY_A(c, s) do { \
        int _k0 = (c) * 32; \
        uint32_t _sB = sb + (uint32_t)(s) * STAGEB; \
        cpa16(_sB + srow0,         Ah + aoff[0] + _k0, avm & 1); \
        cpa16(_sB + srow1,         Ah + aoff[1] + _k0, (avm >> 1) & 1); \
        cpa16(_sB + TILEB + srow0, Al + aoff[0] + _k0, avm & 1); \
        cpa16(_sB + TILEB + srow1, Al + aoff[1] + _k0, (avm >> 1) & 1); \
    } while (0)

#define W_LDG(c) do { \
        const float4* _wp = reinterpret_cast<const float4*>(WE + (size_t)(c) * 32); \
        wr[0] = _wp[0]; wr[1] = _wp[1]; wr[2] = _wp[2]; wr[3] = _wp[3]; \
    } while (0)

#define W_STS(s) do { \
        float _wv[16]; \
        *(float4*)&_wv[0] = wr[0]; *(float4*)&_wv[4] = wr[1]; \
        *(float4*)&_wv[8] = wr[2]; *(float4*)&_wv[12] = wr[3]; \
        __half _hh[16], _hl[16]; \
        _Pragma("unroll") \
        for (int _i = 0; _i < 16; _i++) { \
            _hh[_i] = __float2half_rn(_wv[_i]); \
            _hl[_i] = __float2half_rn(_wv[_i] - __half2float(_hh[_i])); \
        } \
        char* _wh = smem + (uint32_t)(s) * STAGEB + 2 * TILEB + wsts; \
        char* _wl = smem + (uint32_t)(s) * STAGEB + 3 * TILEB + wsts; \
        *(uint4*)(_wh)      = *(uint4*)&_hh[0]; \
        *(uint4*)(_wh + 16) = *(uint4*)&_hh[8]; \
        *(uint4*)(_wl)      = *(uint4*)&_hl[0]; \
        *(uint4*)(_wl + 16) = *(uint4*)&_hl[8]; \
    } while (0)

    // ---- mma mapping: 8 warps, warp tile 32x64 (4M x 2N) ----
    int lane = tid & 31;
    int wid = tid >> 5;
    int wm = (wid & 3) * 32;
    int wn2 = (wid >> 2) * 64;

    uint32_t aRB = (uint32_t)(wm + (lane & 7) + ((lane >> 3) & 1) * 8) * ROWB + ((lane >> 4) & 1) * 16;
    uint32_t bRB = (uint32_t)(wn2 + (lane & 7) + ((lane >> 4) & 1) * 8) * ROWB + ((lane >> 3) & 1) * 16;

    float acc[2][8][4] = {};

    COPY_A(0, 0); CP_COMMIT();
    W_LDG(0);

    for (int c = 0; c < NC; c++) {
        if (c + 1 < NC) { COPY_A(c + 1, (c + 1) & 1); CP_COMMIT(); }
        W_STS(c & 1);
        if (c + 1 < NC) CP_WAIT1(); else CP_WAIT0();
        __syncthreads();
        if (c + 1 < NC) W_LDG(c + 1);

        uint32_t AhB = sb + (uint32_t)(c & 1) * STAGEB;
        uint32_t AlB = AhB + TILEB;
        uint32_t WhB = AhB + 2 * TILEB;
        uint32_t WlB = AhB + 3 * TILEB;
#pragma unroll
        for (int st = 0; st < 2; st++) {
            uint32_t kB = st * 32;
            uint32_t ah[2][4], al[2][4], bb[4][4];
#pragma unroll
            for (int im = 0; im < 2; im++)
                ldsm4(ah[im], AhB + (uint32_t)(im * 16) * ROWB + aRB + kB);
#pragma unroll
            for (int g = 0; g < 4; g++)
                ldsm4(bb[g], WhB + (uint32_t)(g * 16) * ROWB + bRB + kB);
#pragma unroll
            for (int im = 0; im < 2; im++)
#pragma unroll
                for (int in = 0; in < 8; in++)
                    mma_f16(acc[im][in], ah[im], bb[in >> 1][(in & 1) * 2], bb[in >> 1][(in & 1) * 2 + 1]);
#pragma unroll
            for (int im = 0; im < 2; im++)
                ldsm4(al[im], AlB + (uint32_t)(im * 16) * ROWB + aRB + kB);
#pragma unroll
            for (int im = 0; im < 2; im++)
#pragma unroll
                for (int in = 0; in < 8; in++)
                    mma_f16(acc[im][in], al[im], bb[in >> 1][(in & 1) * 2], bb[in >> 1][(in & 1) * 2 + 1]);
#pragma unroll
            for (int g = 0; g < 4; g++)
                ldsm4(bb[g], WlB + (uint32_t)(g * 16) * ROWB + bRB + kB);
#pragma unroll
            for (int im = 0; im < 2; im++)
#pragma unroll
                for (int in = 0; in < 8; in++)
                    mma_f16(acc[im][in], ah[im], bb[in >> 1][(in & 1) * 2], bb[in >> 1][(in & 1) * 2 + 1]);
        }
        __syncthreads();
    }

    // ---- epilogue ----
    int lq = lane >> 2;
    int lr = lane & 3;
    const float* bp = bias ? (bias + (size_t)e * bias_z) : nullptr;
    float* Cz = C ? (C + (size_t)e * czs) : C;
#pragma unroll
    for (int im = 0; im < 2; im++) {
#pragma unroll
        for (int r2 = 0; r2 < 2; r2++) {
            int m = m0 + wm + im * 16 + lq + r2 * 8;
            if (m >= M) continue;
            long crow; float scale = 1.f;
            if (mode == 2)      { crow = perm[base + m]; scale = rowscale[crow]; }
            else if (mode == 1) { crow = base + m; }
            else                { crow = m; }
#pragma unroll
            for (int in = 0; in < 8; in++) {
                int n = n0 + wn2 + in * 8 + lr * 2;
                if (n >= N) continue;
                float v0 = acc[im][in][r2 * 2 + 0];
                float v1 = acc[im][in][r2 * 2 + 1];
                if (bp) { v0 += bp[n]; v1 += bp[n + 1]; }
                if (act == 1) { v0 = fmaxf(v0, 0.f); v1 = fmaxf(v1, 0.f); }
                else if (act == 2) {
                    v0 = (v0 > 20.f) ? v0 : log1pf(__expf(v0));
                    v1 = (v1 > 20.f) ? v1 : log1pf(__expf(v1));
                }
                if (Ch) {
                    __half h0 = __float2half_rn(v0);
                    __half h1 = __float2half_rn(v1);
                    size_t o = (size_t)crow * ldc + n;
                    Ch[o] = h0;     Cl[o]     = __float2half_rn(v0 - __half2float(h0));
                    Ch[o + 1] = h1; Cl[o + 1] = __float2half_rn(v1 - __half2float(h1));
                } else {
                    size_t o = (size_t)crow * ldc + n;
                    Cz[o] = v0 * scale;
                    Cz[o + 1] = v1 * scale;
                }
            }
        }
    }
#undef COPY_A
#undef W_LDG
#undef W_STS
}

// ---------------- split-K reduce for xp ----------------
__global__ void xp_reduce_k() {
    int i = blockIdx.x * 256 + threadIdx.x;     // NTOK*XPD
    float s = 0.f;
#pragma unroll
    for (int j = 0; j < KSPL; j++) s += g_xps[(size_t)j * NTOK * XPD + i];
    g_xp[i] = s;
}

// ---------------- fp16 split helpers ----------------
__device__ __forceinline__ void split2(float v, __half& h, __half& l) {
    h = __float2half_rn(v);
    l = __float2half_rn(v - __half2float(h));
}

__global__ void dtconv_k() {  // xp[:, :DTR] -> g_dah/g_dal (compact)
    int i = blockIdx.x * 256 + threadIdx.x;   // NTOK*DTR
    int t = i >> 6, c = i & 63;
    split2(g_xp[t * XPD + c], g_dah[i], g_dal[i]);
}

// ---------------- embed ----------------
__global__ void embed_k(const int* __restrict__ tok, const float* __restrict__ emb,
                        const float* __restrict__ pos) {
    int i = blockIdx.x * blockDim.x + threadIdx.x;
    int t = i / DM, d = i % DM;
    int l = t % LSEQ;
    float v = emb[(size_t)tok[t] * DM + d] + pos[l * DM + d];
    g_x[i] = v;
    split2(v, g_xh[i], g_xl[i]);
}

// ---------------- conv + silu ----------------
__global__ void conv_silu_k(const float* __restrict__ cw, const float* __restrict__ cb) {
    int i = blockIdx.x * 256 + threadIdx.x;
    if (i >= NTOK * DI) return;
    int t = i / DI, d = i % DI;
    int b = t / LSEQ, l = t % LSEQ;
    float acc = cb[d];
#pragma unroll
    for (int k = 0; k < 4; k++) {
        int ll = l - 3 + k;
        if (ll >= 0) acc += g_uz[(size_t)(b * LSEQ + ll) * (2 * DI) + d] * cw[d * 4 + k];
    }
    float v = acc / (1.f + __expf(-acc));
    g_u[i] = v;
    split2(v, g_uh[i], g_ul[i]);
}

// ---------------- selective scan with cp.async staging ----------------
// grid (BATCH, DI/128), 128 threads. Chunk = 32 steps, double buffered.
// smem floats: U[2][32][128] DT[..] Z[..] B[2][32][16] C[2][32][16]
#define SC_CH   32
#define SC_NC   (LSEQ / SC_CH)
#define SC_U    0
#define SC_DT   8192
#define SC_Z    16384
#define SC_B    24576
#define SC_C    25600
#define SC_SMEM (26624 * 4)

__global__ void __launch_bounds__(128) ssm_scan_k(const float* __restrict__ A_log,
                                                  const float* __restrict__ Dp) {
    int b = blockIdx.x;
    int d0 = blockIdx.y * 128;
    int tid = threadIdx.x;
    int d = d0 + tid;

    float A[DS];
#pragma unroll
    for (int n = 0; n < DS; n++) A[n] = -expf(A_log[d * DS + n]);
    float Dv = Dp[d];
    float h[DS];
#pragma unroll
    for (int n = 0; n < DS; n++) h[n] = 0.f;

    extern __shared__ float smf[];
    uint32_t sbase = smem_u32(smf);

    // issue chunk c into buffer c&1
#define SC_ISSUE(c) do { \
        int _buf = (c) & 1; \
        int _tokb = b * LSEQ + (c) * SC_CH; \
        _Pragma("unroll") \
        for (int _j = 0; _j < 8; _j++) { \
            int _q = _j * 128 + tid; \
            int _s = _q >> 5, _qd = (_q & 31) * 4; \
            uint32_t _o = (uint32_t)(_buf * 4096 + _s * 128 + _qd) * 4; \
            cpa16f(sbase + (SC_U  * 4) + _o, g_u  + (size_t)(_tokb + _s) * DI + d0 + _qd); \
            cpa16f(sbase + (SC_DT * 4) + _o, g_dt + (size_t)(_tokb + _s) * DI + d0 + _qd); \
            cpa16f(sbase + (SC_Z  * 4) + _o, g_uz + (size_t)(_tokb + _s) * (2 * DI) + DI + d0 + _qd); \
        } \
        { int _s = tid >> 2, _qd = (tid & 3) * 4; \
          uint32_t _o = (uint32_t)(_buf * 512 + _s * 16 + _qd) * 4; \
          cpa16f(sbase + (SC_B * 4) + _o, g_xp + (size_t)(_tokb + _s) * XPD + DTR + _qd); \
          cpa16f(sbase + (SC_C * 4) + _o, g_xp + (size_t)(_tokb + _s) * XPD + DTR + DS + _qd); } \
        CP_COMMIT(); \
    } while (0)

    SC_ISSUE(0);
    for (int c = 0; c < SC_NC; c++) {
        if (c + 1 < SC_NC) SC_ISSUE(c + 1);
        if (c + 1 < SC_NC) CP_WAIT1(); else CP_WAIT0();
        __syncthreads();
        int buf = c & 1;
        int tokb = b * LSEQ + c * SC_CH;
        const float* su = smf + SC_U  + buf * 4096 + tid;
        const float* sd = smf + SC_DT + buf * 4096 + tid;
        const float* sz = smf + SC_Z  + buf * 4096 + tid;
        const float* sB = smf + SC_B + buf * 512;
        const float* sC = smf + SC_C + buf * 512;
        for (int s = 0; s < SC_CH; s++) {
            float ut  = su[s * 128];
            float dtt = sd[s * 128];
            float z   = sz[s * 128];
            float du = dtt * ut;
            float yv = 0.f;
#pragma unroll
            for (int n = 0; n < DS; n++) {
                h[n] = __expf(dtt * A[n]) * h[n] + du * sB[s * 16 + n];
                yv += h[n] * sC[s * 16 + n];
            }
            yv += ut * Dv;
            float y = yv * (z / (1.f + __expf(-z)));
            size_t o = (size_t)(tokb + s) * DI + d;
            split2(y, g_yh[o], g_yl[o]);
        }
        __syncthreads();
    }
#undef SC_ISSUE
}

// ---------------- x += LayerNorm(g_t), refresh hi/lo ----------------
__global__ void addln_k(const float* __restrict__ g, const float* __restrict__ bb) {
    int tok = blockIdx.x;
    const float* t = g_t + (size_t)tok * DM;
    float* x = g_x + (size_t)tok * DM;
    int tid = threadIdx.x;
    float v[4]; float s = 0.f;
#pragma unroll
    for (int i = 0; i < 4; i++) { v[i] = t[tid + i * 256]; s += v[i]; }
    __shared__ float sm[256];
    sm[tid] = s; __syncthreads();
    for (int st = 128; st > 0; st >>= 1) { if (tid < st) sm[tid] += sm[tid + st]; __syncthreads(); }
    float mean = sm[0] / DM;
    __syncthreads();
    float q = 0.f;
#pragma unroll
    for (int i = 0; i < 4; i++) { float dd = v[i] - mean; q += dd * dd; }
    sm[tid] = q; __syncthreads();
    for (int st = 128; st > 0; st >>= 1) { if (tid < st) sm[tid] += sm[tid + st]; __syncthreads(); }
    float rstd = rsqrtf(sm[0] / DM + 1e-5f);
#pragma unroll
    for (int i = 0; i < 4; i++) {
        int d = tid + i * 256;
        float nx = x[d] + (v[i] - mean) * rstd * g[d] + bb[d];
        x[d] = nx;
        split2(nx, g_xh[(size_t)tok * DM + d], g_xl[(size_t)tok * DM + d]);
    }
}

// ---------------- MoE gate ----------------
__global__ void gate_k(const float* __restrict__ gw, const float* __restrict__ gb) {
    int tok = blockIdx.x;
    const float* x = g_x + (size_t)tok * DM;
    int tid = threadIdx.x;
    float p[NEXP];
#pragma unroll
    for (int e = 0; e < NEXP; e++) p[e] = 0.f;
    for (int d = tid; d < DM; d += 256) {
        float xv = x[d];
#pragma unroll
        for (int e = 0; e < NEXP; e++) p[e] += xv * gw[e * DM + d];
    }
    __shared__ float sm[NEXP][256];
#pragma unroll
    for (int e = 0; e < NEXP; e++) sm[e][tid] = p[e];
    __syncthreads();
    for (int st = 128; st > 0; st >>= 1) {
        if (tid < st)
#pragma unroll
            for (int e = 0; e < NEXP; e++) sm[e][tid] += sm[e][tid + st];
        __syncthreads();
    }
    if (tid == 0) {
        float m = -1e30f; int bi = 0;
        float lg[NEXP];
#pragma unroll
        for (int e = 0; e < NEXP; e++) {
            lg[e] = sm[e][0] + gb[e];
            if (lg[e] > m) { m = lg[e]; bi = e; }
        }
        float ssum = 0.f;
#pragma unroll
        for (int e = 0; e < NEXP; e++) ssum += __expf(lg[e] - m);
        g_eidx[tok] = bi;
        g_ew[tok] = 1.f / ssum;
        atomicAdd(&g_cnt[bi], 1);
    }
}

__global__ void route_reset_k() { if (threadIdx.x < NEXP) { g_cnt[threadIdx.x] = 0; g_fill[threadIdx.x] = 0; } }
__global__ void route_offsets_k() {
    if (threadIdx.x == 0) { int o = 0; for (int e = 0; e < NEXP; e++) { g_off[e] = o; o += g_cnt[e]; } }
}
__global__ void route_scatter_k() {
    int tok = blockIdx.x * 256 + threadIdx.x;
    if (tok < NTOK) {
        int e = g_eidx[tok];
        int p = g_off[e] + atomicAdd(&g_fill[e], 1);
        g_perm[p] = tok;
    }
}

// ---------------- pooling + head ----------------
__global__ void cntb_reset_k() { if (threadIdx.x < BATCH) g_cntb[threadIdx.x] = 0; }

__global__ void rowmask_k() {
    int tok = blockIdx.x;
    int tid = threadIdx.x;
    float s = 0.f;
#pragma unroll
    for (int i = 0; i < 4; i++) s += g_x[(size_t)tok * DM + tid + i * 256];
    __shared__ float sm[256];
    sm[tid] = s; __syncthreads();
    for (int st = 128; st > 0; st >>= 1) { if (tid < st) sm[tid] += sm[tid + st]; __syncthreads(); }
    if (tid == 0) {
        float m = (sm[0] != 0.f) ? 1.f : 0.f;
        g_mask[tok] = m;
        if (m != 0.f) atomicAdd(&g_cntb[tok / LSEQ], 1);
    }
}

__global__ void pool_k() {
    int b = blockIdx.x;
    int d = blockIdx.y * 256 + threadIdx.x;
    float acc = 0.f;
    for (int l = 0; l < LSEQ; l++)
        acc += g_x[(size_t)(b * LSEQ + l) * DM + d] * g_mask[b * LSEQ + l];
    g_pooled[b * DM + d] = acc / fmaxf((float)g_cntb[b], 1.f);
}

__global__ void head_k(const float* __restrict__ w1, const float* __restrict__ b1,
                       const float* __restrict__ w2, const float* __restrict__ b2,
                       float* __restrict__ out) {
    int b = blockIdx.x;
    int j = threadIdx.x;
    const float* p = g_pooled + b * DM;
    float acc = b1[j];
    for (int k = 0; k < DM; k++) acc += p[k] * w1[j * DM + k];
    __shared__ float h[128];
    h[j] = fmaxf(acc, 0.f);
    __syncthreads();
    if (j < 2) {
        float o = b2[j];
        for (int k = 0; k < 128; k++) o += h[k] * w2[j * 128 + k];
        out[b * 2 + j] = o;
    }
}

// ---------------- launch ----------------
extern "C" void kernel_launch(void* const* d_in, const int* in_sizes, int n_in,
                              void* d_out, int out_size) {
    const int*   tok    = (const int*)  d_in[0];
    const float* emb    = (const float*)d_in[1];
    const float* pos    = (const float*)d_in[2];
    const float* in_w   = (const float*)d_in[3];
    const float* conv_w = (const float*)d_in[4];
    const float* conv_b = (const float*)d_in[5];
    const float* xp_w   = (const float*)d_in[6];
    const float* dt_w   = (const float*)d_in[7];
    const float* dt_b   = (const float*)d_in[8];
    const float* A_log  = (const float*)d_in[9];
    const float* D_ssm  = (const float*)d_in[10];
    const float* out_w  = (const float*)d_in[11];
    const float* ln1_g  = (const float*)d_in[12];
    const float* ln1_b  = (const float*)d_in[13];
    const float* ln2_g  = (const float*)d_in[14];
    const float* ln2_b  = (const float*)d_in[15];
    const float* gate_w = (const float*)d_in[16];
    const float* gate_b = (const float*)d_in[17];
    const float* e_w1   = (const float*)d_in[18];
    const float* e_b1   = (const float*)d_in[19];
    const float* e_w2   = (const float*)d_in[20];
    const float* e_b2   = (const float*)d_in[21];
    const float* fc1_w  = (const float*)d_in[22];
    const float* fc1_b  = (const float*)d_in[23];
    const float* fc2_w  = (const float*)d_in[24];
    const float* fc2_b  = (const float*)d_in[25];
    float* out = (float*)d_out;

    cudaFuncSetAttribute(mma_gemm, cudaFuncAttributeMaxDynamicSharedMemorySize, SM_TOT);
    cudaFuncSetAttribute(ssm_scan_k, cudaFuncAttributeMaxDynamicSharedMemorySize, SC_SMEM);

    float *puz, *pxp, *pxps, *pdt, *pt, *pew;
    __half *pxh, *pxl, *puh, *pul, *pyh, *pyl, *phh, *phl, *pdah, *pdal;
    int *pcnt, *poff, *pperm;
    cudaGetSymbolAddress((void**)&puz,  g_uz);
    cudaGetSymbolAddress((void**)&pxp,  g_xp);
    cudaGetSymbolAddress((void**)&pxps, g_xps);
    cudaGetSymbolAddress((void**)&pdt,  g_dt);
    cudaGetSymbolAddress((void**)&pt,   g_t);
    cudaGetSymbolAddress((void**)&pew,  g_ew);
    cudaGetSymbolAddress((void**)&pxh,  g_xh);
    cudaGetSymbolAddress((void**)&pxl,  g_xl);
    cudaGetSymbolAddress((void**)&puh,  g_uh);
    cudaGetSymbolAddress((void**)&pul,  g_ul);
    cudaGetSymbolAddress((void**)&pyh,  g_yh);
    cudaGetSymbolAddress((void**)&pyl,  g_yl);
    cudaGetSymbolAddress((void**)&phh,  g_hh);
    cudaGetSymbolAddress((void**)&phl,  g_hl);
    cudaGetSymbolAddress((void**)&pdah, g_dah);
    cudaGetSymbolAddress((void**)&pdal, g_dal);
    cudaGetSymbolAddress((void**)&pcnt, g_cnt);
    cudaGetSymbolAddress((void**)&poff, g_off);
    cudaGetSymbolAddress((void**)&pperm,g_perm);

    embed_k<<<(NTOK * DM) / 256, 256>>>(tok, emb, pos);

    for (int l = 0; l < 2; l++) {
        const float* in_w_l  = in_w  + (size_t)l * 2 * DI * DM;
        const float* xp_w_l  = xp_w  + (size_t)l * XPD * DI;
        const float* dt_w_l  = dt_w  + (size_t)l * DI * DTR;
        const float* out_w_l = out_w + (size_t)l * DM * DI;
        const float* e_w1_l  = e_w1  + (size_t)l * NEXP * HEXP * DM;
        const float* e_w2_l  = e_w2  + (size_t)l * NEXP * DM * HEXP;

        // in_proj: uz = x @ in_w^T     [4096 x 4096], K=1024
        mma_gemm<<<dim3(32, 32, 1), 256, SM_TOT>>>(
            pxh, pxl, DM, 0, in_w_l, DM, 0, puz, 2 * DI, 0, nullptr, nullptr,
            nullptr, 0, NTOK, nullptr, nullptr, nullptr, nullptr, 0, 2 * DI, DM, 0);

        conv_silu_k<<<(NTOK * DI) / 256, 256>>>(conv_w + (size_t)l * DI * 4, conv_b + (size_t)l * DI);

        // xp = u @ xp_w^T  [4096 x 96], K=2048 split-K x8 -> g_xps, then reduce
        mma_gemm<<<dim3(32, 1, KSPL), 256, SM_TOT>>>(
            puh, pul, DI, DI / KSPL, xp_w_l, DI, DI / KSPL, pxps, XPD, (size_t)NTOK * XPD,
            nullptr, nullptr, nullptr, 0, NTOK, nullptr, nullptr, nullptr, nullptr,
            0, XPD, DI / KSPL, 0);
        xp_reduce_k<<<(NTOK * XPD) / 256, 256>>>();

        // dt = softplus(xp[:,:64] @ dt_w^T + dt_b)   [4096 x 2048], K=64
        dtconv_k<<<(NTOK * DTR) / 256, 256>>>();
        mma_gemm<<<dim3(32, 16, 1), 256, SM_TOT>>>(
            pdah, pdal, DTR, 0, dt_w_l, DTR, 0, pdt, DI, 0, nullptr, nullptr,
            dt_b + (size_t)l * DI, 0, NTOK, nullptr, nullptr, nullptr, nullptr, 0, DI, DTR, 2);

        // scan
        ssm_scan_k<<<dim3(BATCH, DI / 128), 128, SC_SMEM>>>(
            A_log + (size_t)l * DI * DS, D_ssm + (size_t)l * DI);

        // out: t = y @ out_w^T         [4096 x 1024], K=2048
        mma_gemm<<<dim3(32, 8, 1), 256, SM_TOT>>>(
            pyh, pyl, DI, 0, out_w_l, DI, 0, pt, DM, 0, nullptr, nullptr,
            nullptr, 0, NTOK, nullptr, nullptr, nullptr, nullptr, 0, DM, DI, 0);

        addln_k<<<NTOK, 256>>>(ln1_g + (size_t)l * DM, ln1_b + (size_t)l * DM);

        // MoE routing
        route_reset_k<<<1, 32>>>();
        gate_k<<<NTOK, 256>>>(gate_w + (size_t)l * NEXP * DM, gate_b + (size_t)l * NEXP);
        route_offsets_k<<<1, 1>>>();
        route_scatter_k<<<NTOK / 256, 256>>>();

        // moe1: h = relu(gather(x) @ w1[e]^T + b1[e]) -> fp16 hi/lo
        mma_gemm<<<dim3(32, 8, NEXP), 256, SM_TOT>>>(
            pxh, pxl, DM, 0, e_w1_l, DM, (size_t)HEXP * DM, nullptr, HEXP, 0, phh, phl,
            e_b1 + (size_t)l * NEXP * HEXP, HEXP, 0, pcnt, poff, pperm, nullptr, 1, HEXP, DM, 1);

        // moe2: t = scatter(topw * (h @ w2[e]^T + b2[e]))
        mma_gemm<<<dim3(32, 8, NEXP), 256, SM_TOT>>>(
            phh, phl, HEXP, 0, e_w2_l, HEXP, (size_t)DM * HEXP, pt, DM, 0, nullptr, nullptr,
            e_b2 + (size_t)l * NEXP * DM, DM, 0, pcnt, poff, pperm, pew, 2, DM, HEXP, 0);

        addln_k<<<NTOK, 256>>>(ln2_g + (size_t)l * DM, ln2_b + (size_t)l * DM);
    }

    cntb_reset_k<<<1, 32>>>();
    rowmask_k<<<NTOK, 256>>>();
    pool_k<<<dim3(BATCH, DM / 256), 256>>>();
    head_k<<<BATCH, 128>>>(fc1_w, fc1_b, fc2_w, fc2_b, out);
}

// round 9
// speedup vs baseline: 1.9297x; 1.0092x over previous
#include <cuda_runtime.h>
#include <cuda_fp16.h>
#include <math.h>
#include <stdint.h>

// ---------------- problem constants ----------------
#define NTOK  4096
#define LSEQ  1024
#define BATCH 4
#define DM    1024
#define DI    2048
#define DS    16
#define DTR   64
#define XPD   96
#define NEXP  8
#define HEXP  1024
#define KSPL  8               // split-K factor for xp gemm
#define SEG   8               // scan segments
#define SLEN  (LSEQ / SEG)    // 128

// ---------------- device scratch ----------------
__device__ float g_x [NTOK*DM];
__device__ float g_uz[NTOK*2*DI];
__device__ float g_u [NTOK*DI];
__device__ float g_xp[NTOK*XPD];
__device__ float g_xps[KSPL*NTOK*XPD];
__device__ float g_dt[NTOK*DI];
__device__ float g_pp[2*NTOK*DM];          // split-K partials (out / moe1 / moe2)
__device__ float g_mask[NTOK];
__device__ float g_pooled[BATCH*DM];
__device__ int   g_eidx[NTOK];
__device__ float g_ew  [NTOK];
__device__ int   g_perm[NTOK];
__device__ int   g_cnt[NEXP], g_off[NEXP], g_fill[NEXP], g_cntb[BATCH];

// scan segment state
__device__ float g_hseg[BATCH*SEG*DI*DS];
__device__ float g_hin [BATCH*SEG*DI*DS];
__device__ float g_sdt [BATCH*SEG*DI];

// fp16 hi/lo split buffers (activations only)
__device__ __half g_xh[NTOK*DM],  g_xl[NTOK*DM];
__device__ __half g_uh[NTOK*DI],  g_ul[NTOK*DI];
__device__ __half g_yh[NTOK*DI],  g_yl[NTOK*DI];
__device__ __half g_hh[NTOK*HEXP],g_hl[NTOK*HEXP];
__device__ __half g_dah[NTOK*DTR],g_dal[NTOK*DTR];

// ---------------- PTX helpers (base ISA only) ----------------
__device__ __forceinline__ uint32_t smem_u32(const void* p) {
    uint32_t a;
    asm("{ .reg .u64 t; cvta.to.shared.u64 t, %1; cvt.u32.u64 %0, t; }" : "=r"(a) : "l"(p));
    return a;
}
__device__ __forceinline__ void ldsm4(uint32_t* r, uint32_t addr) {
    asm volatile("ldmatrix.sync.aligned.m8n8.x4.shared.b16 {%0,%1,%2,%3}, [%4];"
        : "=r"(r[0]), "=r"(r[1]), "=r"(r[2]), "=r"(r[3]) : "r"(addr));
}
__device__ __forceinline__ void mma_f16(float* c, const uint32_t* a, uint32_t b0, uint32_t b1) {
    asm volatile("mma.sync.aligned.m16n8k16.row.col.f32.f16.f16.f32 "
        "{%0,%1,%2,%3}, {%4,%5,%6,%7}, {%8,%9}, {%0,%1,%2,%3};"
        : "+f"(c[0]), "+f"(c[1]), "+f"(c[2]), "+f"(c[3])
        : "r"(a[0]), "r"(a[1]), "r"(a[2]), "r"(a[3]), "r"(b0), "r"(b1));
}
__device__ __forceinline__ void cpa16(uint32_t saddr, const void* g, bool v) {
    int sz = v ? 16 : 0;
    asm volatile("cp.async.cg.shared.global [%0], [%1], 16, %2;"
        :: "r"(saddr), "l"(g), "r"(sz));
}
#define CP_COMMIT() asm volatile("cp.async.commit_group;" ::: "memory")
#define CP_WAIT1()  asm volatile("cp.async.wait_group 1;" ::: "memory")
#define CP_WAIT0()  asm volatile("cp.async.wait_group 0;" ::: "memory")

// smem geometry: K-chunk 32 fp16 = 64B/row, padded to 80B
#define ROWB   80
#define TILEB  10240
#define STAGEB 40960
#define SM_TOT 81920

// ============ fused-split fp16 mma.sync GEMM ============
// grid.y = nyb * ksplit; ks = y/nyb selects K-segment, partials to C + ks*czs.
// bias applied only on ks==0. act only valid when ksplit==1 (callers ensure).
__global__ void __launch_bounds__(256, 2)
mma_gemm(const __half* __restrict__ Ah, const __half* __restrict__ Al, int lda,
         const float* __restrict__ W32, int ldw, size_t wz,
         float* __restrict__ C, int ldc, size_t czs,
         __half* __restrict__ Ch, __half* __restrict__ Cl,
         const float* __restrict__ bias, int bias_z,
         int M_fixed, const int* __restrict__ cntp, const int* __restrict__ offp,
         const int* __restrict__ perm, const float* __restrict__ rowscale,
         int mode, int N, int K, int nyb, int act)
{
    int e = blockIdx.z;
    int M = cntp ? cntp[e] : M_fixed;
    int base = offp ? offp[e] : 0;
    int m0 = blockIdx.x * 128;
    if (m0 >= M) return;
    int yy = blockIdx.y;
    int ks = yy / nyb;
    int n0 = (yy - ks * nyb) * 128;

    extern __shared__ char smem[];
    uint32_t sb = smem_u32(smem);
    int tid = threadIdx.x;

    int sub = tid & 3;
    int r0 = tid >> 2;
    size_t aoff[2]; uint32_t avm = 0;
#pragma unroll
    for (int i = 0; i < 2; i++) {
        int mm = m0 + r0 + 64 * i;
        bool av = mm < M;
        if (av) avm |= 1u << i;
        int ar;
        if (mode == 1)      ar = av ? perm[base + mm] : 0;
        else if (mode == 2) ar = base + (av ? mm : 0);
        else                ar = av ? mm : 0;
        aoff[i] = (size_t)ar * lda + sub * 8 + (size_t)ks * K;
    }
    uint32_t srow0 = r0 * ROWB + sub * 16;
    uint32_t srow1 = (r0 + 64) * ROWB + sub * 16;

    int wrow_l = tid >> 1;
    int wn = n0 + wrow_l;
    if (wn >= N) wn = 0;
    int khalf = (tid & 1) * 16;
    const float* WE = W32 + (size_t)e * wz + (size_t)wn * ldw + khalf + (size_t)ks * K;
    uint32_t wsts = (uint32_t)wrow_l * ROWB + (tid & 1) * 32;

    const int NC = K / 32;
    float4 wr[4];

#define COPY_A(c, s) do { \
        int _k0 = (c) * 32; \
        uint32_t _sB = sb + (uint32_t)(s) * STAGEB; \
        cpa16(_sB + srow0,         Ah + aoff[0] + _k0, avm & 1); \
        cpa16(_sB + srow1,         Ah + aoff[1] + _k0, (avm >> 1) & 1); \
        cpa16(_sB + TILEB + srow0, Al + aoff[0] + _k0, avm & 1); \
        cpa16(_sB + TILEB + srow1, Al + aoff[1] + _k0, (avm >> 1) & 1); \
    } while (0)

#define W_LDG(c) do { \
        const float4* _wp = reinterpret_cast<const float4*>(WE + (size_t)(c) * 32); \
        wr[0] = _wp[0]; wr[1] = _wp[1]; wr[2] = _wp[2]; wr[3] = _wp[3]; \
    } while (0)

#define W_STS(s) do { \
        float _wv[16]; \
        *(float4*)&_wv[0] = wr[0]; *(float4*)&_wv[4] = wr[1]; \
        *(float4*)&_wv[8] = wr[2]; *(float4*)&_wv[12] = wr[3]; \
        __half _hh[16], _hl[16]; \
        _Pragma("unroll") \
        for (int _i = 0; _i < 16; _i++) { \
            _hh[_i] = __float2half_rn(_wv[_i]); \
            _hl[_i] = __float2half_rn(_wv[_i] - __half2float(_hh[_i])); \
        } \
        char* _wh = smem + (uint32_t)(s) * STAGEB + 2 * TILEB + wsts; \
        char* _wl = smem + (uint32_t)(s) * STAGEB + 3 * TILEB + wsts; \
        *(uint4*)(_wh)      = *(uint4*)&_hh[0]; \
        *(uint4*)(_wh + 16) = *(uint4*)&_hh[8]; \
        *(uint4*)(_wl)      = *(uint4*)&_hl[0]; \
        *(uint4*)(_wl + 16) = *(uint4*)&_hl[8]; \
    } while (0)

    int lane = tid & 31;
    int wid = tid >> 5;
    int wm = (wid & 3) * 32;
    int wn2 = (wid >> 2) * 64;

    uint32_t aRB = (uint32_t)(wm + (lane & 7) + ((lane >> 3) & 1) * 8) * ROWB + ((lane >> 4) & 1) * 16;
    uint32_t bRB = (uint32_t)(wn2 + (lane & 7) + ((lane >> 4) & 1) * 8) * ROWB + ((lane >> 3) & 1) * 16;

    float acc[2][8][4] = {};

    COPY_A(0, 0); CP_COMMIT();
    W_LDG(0);

    for (int c = 0; c < NC; c++) {
        if (c + 1 < NC) { COPY_A(c + 1, (c + 1) & 1); CP_COMMIT(); }
        W_STS(c & 1);
        if (c + 1 < NC) CP_WAIT1(); else CP_WAIT0();
        __syncthreads();
        if (c + 1 < NC) W_LDG(c + 1);

        uint32_t AhB = sb + (uint32_t)(c & 1) * STAGEB;
        uint32_t AlB = AhB + TILEB;
        uint32_t WhB = AhB + 2 * TILEB;
        uint32_t WlB = AhB + 3 * TILEB;
#pragma unroll
        for (int st = 0; st < 2; st++) {
            uint32_t kB = st * 32;
            uint32_t ah[2][4], al[2][4], bb[4][4];
#pragma unroll
            for (int im = 0; im < 2; im++)
                ldsm4(ah[im], AhB + (uint32_t)(im * 16) * ROWB + aRB + kB);
#pragma unroll
            for (int g = 0; g < 4; g++)
                ldsm4(bb[g], WhB + (uint32_t)(g * 16) * ROWB + bRB + kB);
#pragma unroll
            for (int im = 0; im < 2; im++)
#pragma unroll
                for (int in = 0; in < 8; in++)
                    mma_f16(acc[im][in], ah[im], bb[in >> 1][(in & 1) * 2], bb[in >> 1][(in & 1) * 2 + 1]);
#pragma unroll
            for (int im = 0; im < 2; im++)
                ldsm4(al[im], AlB + (uint32_t)(im * 16) * ROWB + aRB + kB);
#pragma unroll
            for (int im = 0; im < 2; im++)
#pragma unroll
                for (int in = 0; in < 8; in++)
                    mma_f16(acc[im][in], al[im], bb[in >> 1][(in & 1) * 2], bb[in >> 1][(in & 1) * 2 + 1]);
#pragma unroll
            for (int g = 0; g < 4; g++)
                ldsm4(bb[g], WlB + (uint32_t)(g * 16) * ROWB + bRB + kB);
#pragma unroll
            for (int im = 0; im < 2; im++)
#pragma unroll
                for (int in = 0; in < 8; in++)
                    mma_f16(acc[im][in], ah[im], bb[in >> 1][(in & 1) * 2], bb[in >> 1][(in & 1) * 2 + 1]);
        }
        __syncthreads();
    }

    // ---- epilogue ----
    int lq = lane >> 2;
    int lr = lane & 3;
    const float* bp = (bias && ks == 0) ? (bias + (size_t)e * bias_z) : nullptr;
    float* Cz = C ? (C + (size_t)ks * czs) : C;
#pragma unroll
    for (int im = 0; im < 2; im++) {
#pragma unroll
        for (int r2 = 0; r2 < 2; r2++) {
            int m = m0 + wm + im * 16 + lq + r2 * 8;
            if (m >= M) continue;
            long crow; float scale = 1.f;
            if (mode == 2)      { crow = perm[base + m]; scale = rowscale[crow]; }
            else if (mode == 1) { crow = base + m; }
            else                { crow = m; }
#pragma unroll
            for (int in = 0; in < 8; in++) {
                int n = n0 + wn2 + in * 8 + lr * 2;
                if (n >= N) continue;
                float v0 = acc[im][in][r2 * 2 + 0];
                float v1 = acc[im][in][r2 * 2 + 1];
                if (bp) { v0 += bp[n]; v1 += bp[n + 1]; }
                if (act == 1) { v0 = fmaxf(v0, 0.f); v1 = fmaxf(v1, 0.f); }
                else if (act == 2) {
                    v0 = (v0 > 20.f) ? v0 : log1pf(__expf(v0));
                    v1 = (v1 > 20.f) ? v1 : log1pf(__expf(v1));
                }
                if (Ch) {
                    __half h0 = __float2half_rn(v0);
                    __half h1 = __float2half_rn(v1);
                    size_t o = (size_t)crow * ldc + n;
                    Ch[o] = h0;     Cl[o]     = __float2half_rn(v0 - __half2float(h0));
                    Ch[o + 1] = h1; Cl[o + 1] = __float2half_rn(v1 - __half2float(h1));
                } else {
                    size_t o = (size_t)crow * ldc + n;
                    Cz[o] = v0 * scale;
                    Cz[o + 1] = v1 * scale;
                }
            }
        }
    }
#undef COPY_A
#undef W_LDG
#undef W_STS
}

// ---------------- split-K reduce for xp ----------------
__global__ void xp_reduce_k() {
    int i = blockIdx.x * 256 + threadIdx.x;
    float s = 0.f;
#pragma unroll
    for (int j = 0; j < KSPL; j++) s += g_xps[(size_t)j * NTOK * XPD + i];
    g_xp[i] = s;
}

// ---------------- fp16 split helpers ----------------
__device__ __forceinline__ void split2(float v, __half& h, __half& l) {
    h = __float2half_rn(v);
    l = __float2half_rn(v - __half2float(h));
}

__global__ void dtconv_k() {
    int i = blockIdx.x * 256 + threadIdx.x;
    int t = i >> 6, c = i & 63;
    split2(g_xp[t * XPD + c], g_dah[i], g_dal[i]);
}

// ---------------- embed ----------------
__global__ void embed_k(const int* __restrict__ tok, const float* __restrict__ emb,
                        const float* __restrict__ pos) {
    int i = blockIdx.x * blockDim.x + threadIdx.x;
    int t = i / DM, d = i % DM;
    int l = t % LSEQ;
    float v = emb[(size_t)tok[t] * DM + d] + pos[l * DM + d];
    g_x[i] = v;
    split2(v, g_xh[i], g_xl[i]);
}

// ---------------- conv + silu ----------------
__global__ void conv_silu_k(const float* __restrict__ cw, const float* __restrict__ cb) {
    int i = blockIdx.x * 256 + threadIdx.x;
    if (i >= NTOK * DI) return;
    int t = i / DI, d = i % DI;
    int b = t / LSEQ, l = t % LSEQ;
    float acc = cb[d];
#pragma unroll
    for (int k = 0; k < 4; k++) {
        int ll = l - 3 + k;
        if (ll >= 0) acc += g_uz[(size_t)(b * LSEQ + ll) * (2 * DI) + d] * cw[d * 4 + k];
    }
    float v = acc / (1.f + __expf(-acc));
    g_u[i] = v;
    split2(v, g_uh[i], g_ul[i]);
}

// ---------------- segmented selective scan ----------------
// phase 1: per-segment local scan (h from 0) + sum(dt); no outputs
__global__ void __launch_bounds__(128) scan_p1(const float* __restrict__ A_log) {
    int b = blockIdx.x, seg = blockIdx.z;
    int d = blockIdx.y * 128 + threadIdx.x;
    int tid = threadIdx.x;
    int tokb = b * LSEQ + seg * SLEN;

    __shared__ float sB[SLEN][DS];
    for (int i = tid; i < SLEN * DS; i += 128) {
        int s = i >> 4, n = i & 15;
        sB[s][n] = g_xp[(size_t)(tokb + s) * XPD + DTR + n];
    }
    __syncthreads();

    float A[DS];
#pragma unroll
    for (int n = 0; n < DS; n++) A[n] = -expf(A_log[d * DS + n]);
    float h[DS];
#pragma unroll
    for (int n = 0; n < DS; n++) h[n] = 0.f;
    float sdt = 0.f;

    for (int s = 0; s < SLEN; s++) {
        float ut  = g_u [(size_t)(tokb + s) * DI + d];
        float dtt = g_dt[(size_t)(tokb + s) * DI + d];
        sdt += dtt;
        float du = dtt * ut;
#pragma unroll
        for (int n = 0; n < DS; n++)
            h[n] = __expf(dtt * A[n]) * h[n] + du * sB[s][n];
    }
    size_t idx = ((size_t)(b * SEG + seg) * DI + d) * DS;
#pragma unroll
    for (int n = 0; n < DS; n++) g_hseg[idx + n] = h[n];
    g_sdt[(size_t)(b * SEG + seg) * DI + d] = sdt;
}

// combine: sequential over segments (cheap), produce h_in per segment
__global__ void __launch_bounds__(128) scan_comb(const float* __restrict__ A_log) {
    int b = blockIdx.x;
    int d = blockIdx.y * 128 + threadIdx.x;
    float A[DS];
#pragma unroll
    for (int n = 0; n < DS; n++) A[n] = -expf(A_log[d * DS + n]);
    float h[DS];
#pragma unroll
    for (int n = 0; n < DS; n++) h[n] = 0.f;
    for (int seg = 0; seg < SEG; seg++) {
        size_t idx = ((size_t)(b * SEG + seg) * DI + d) * DS;
#pragma unroll
        for (int n = 0; n < DS; n++) g_hin[idx + n] = h[n];
        float sdt = g_sdt[(size_t)(b * SEG + seg) * DI + d];
#pragma unroll
        for (int n = 0; n < DS; n++)
            h[n] = __expf(sdt * A[n]) * h[n] + g_hseg[idx + n];
    }
}

// phase 2: rescan with corrected h_in, produce y * silu(z) -> fp16 split
__global__ void __launch_bounds__(128) scan_p2(const float* __restrict__ A_log,
                                               const float* __restrict__ Dp) {
    int b = blockIdx.x, seg = blockIdx.z;
    int d = blockIdx.y * 128 + threadIdx.x;
    int tid = threadIdx.x;
    int tokb = b * LSEQ + seg * SLEN;

    __shared__ float sBC[SLEN][2 * DS];
    for (int i = tid; i < SLEN * 2 * DS; i += 128) {
        int s = i >> 5, n = i & 31;
        sBC[s][n] = g_xp[(size_t)(tokb + s) * XPD + DTR + n];
    }
    __syncthreads();

    float A[DS];
#pragma unroll
    for (int n = 0; n < DS; n++) A[n] = -expf(A_log[d * DS + n]);
    float Dv = Dp[d];
    float h[DS];
    size_t idx = ((size_t)(b * SEG + seg) * DI + d) * DS;
#pragma unroll
    for (int n = 0; n < DS; n++) h[n] = g_hin[idx + n];

    for (int s = 0; s < SLEN; s++) {
        float ut  = g_u [(size_t)(tokb + s) * DI + d];
        float dtt = g_dt[(size_t)(tokb + s) * DI + d];
        float z   = g_uz[(size_t)(tokb + s) * (2 * DI) + DI + d];
        float du = dtt * ut;
        float yv = 0.f;
#pragma unroll
        for (int n = 0; n < DS; n++) {
            h[n] = __expf(dtt * A[n]) * h[n] + du * sBC[s][n];
            yv += h[n] * sBC[s][DS + n];
        }
        yv += ut * Dv;
        float y = yv * (z / (1.f + __expf(-z)));
        size_t o = (size_t)(tokb + s) * DI + d;
        split2(y, g_yh[o], g_yl[o]);
    }
}

// ---------------- x += LayerNorm(t0 + t1), refresh hi/lo ----------------
__global__ void addln_k(const float* __restrict__ g, const float* __restrict__ bb,
                        const float* __restrict__ t0, const float* __restrict__ t1) {
    int tok = blockIdx.x;
    int tid = threadIdx.x;
    float* x = g_x + (size_t)tok * DM;
    float v[4]; float s = 0.f;
#pragma unroll
    for (int i = 0; i < 4; i++) {
        size_t o = (size_t)tok * DM + tid + i * 256;
        v[i] = t0[o] + t1[o];
        s += v[i];
    }
    __shared__ float sm[256];
    sm[tid] = s; __syncthreads();
    for (int st = 128; st > 0; st >>= 1) { if (tid < st) sm[tid] += sm[tid + st]; __syncthreads(); }
    float mean = sm[0] / DM;
    __syncthreads();
    float q = 0.f;
#pragma unroll
    for (int i = 0; i < 4; i++) { float dd = v[i] - mean; q += dd * dd; }
    sm[tid] = q; __syncthreads();
    for (int st = 128; st > 0; st >>= 1) { if (tid < st) sm[tid] += sm[tid + st]; __syncthreads(); }
    float rstd = rsqrtf(sm[0] / DM + 1e-5f);
#pragma unroll
    for (int i = 0; i < 4; i++) {
        int d = tid + i * 256;
        float nx = x[d] + (v[i] - mean) * rstd * g[d] + bb[d];
        x[d] = nx;
        split2(nx, g_xh[(size_t)tok * DM + d], g_xl[(size_t)tok * DM + d]);
    }
}

// ---------------- moe1 combine: relu(p0+p1+b1[e]) -> fp16 split ----------------
__global__ void moe1_comb(const float* __restrict__ b1) {
    int i = blockIdx.x * 256 + threadIdx.x;     // NTOK*HEXP
    int r = i >> 10, col = i & 1023;
    int e = g_eidx[g_perm[r]];
    float v = g_pp[i] + g_pp[NTOK * HEXP + i] + b1[e * HEXP + col];
    v = fmaxf(v, 0.f);
    split2(v, g_hh[i], g_hl[i]);
}

// ---------------- MoE gate ----------------
__global__ void gate_k(const float* __restrict__ gw, const float* __restrict__ gb) {
    int tok = blockIdx.x;
    const float* x = g_x + (size_t)tok * DM;
    int tid = threadIdx.x;
    float p[NEXP];
#pragma unroll
    for (int e = 0; e < NEXP; e++) p[e] = 0.f;
    for (int d = tid; d < DM; d += 256) {
        float xv = x[d];
#pragma unroll
        for (int e = 0; e < NEXP; e++) p[e] += xv * gw[e * DM + d];
    }
    __shared__ float sm[NEXP][256];
#pragma unroll
    for (int e = 0; e < NEXP; e++) sm[e][tid] = p[e];
    __syncthreads();
    for (int st = 128; st > 0; st >>= 1) {
        if (tid < st)
#pragma unroll
            for (int e = 0; e < NEXP; e++) sm[e][tid] += sm[e][tid + st];
        __syncthreads();
    }
    if (tid == 0) {
        float m = -1e30f; int bi = 0;
        float lg[NEXP];
#pragma unroll
        for (int e = 0; e < NEXP; e++) {
            lg[e] = sm[e][0] + gb[e];
            if (lg[e] > m) { m = lg[e]; bi = e; }
        }
        float ssum = 0.f;
#pragma unroll
        for (int e = 0; e < NEXP; e++) ssum += __expf(lg[e] - m);
        g_eidx[tok] = bi;
        g_ew[tok] = 1.f / ssum;
        atomicAdd(&g_cnt[bi], 1);
    }
}

__global__ void route_reset_k() { if (threadIdx.x < NEXP) { g_cnt[threadIdx.x] = 0; g_fill[threadIdx.x] = 0; } }
__global__ void route_offsets_k() {
    if (threadIdx.x == 0) { int o = 0; for (int e = 0; e < NEXP; e++) { g_off[e] = o; o += g_cnt[e]; } }
}
__global__ void route_scatter_k() {
    int tok = blockIdx.x * 256 + threadIdx.x;
    if (tok < NTOK) {
        int e = g_eidx[tok];
        int p = g_off[e] + atomicAdd(&g_fill[e], 1);
        g_perm[p] = tok;
    }
}

// ---------------- pooling + head ----------------
__global__ void cntb_reset_k() { if (threadIdx.x < BATCH) g_cntb[threadIdx.x] = 0; }

__global__ void rowmask_k() {
    int tok = blockIdx.x;
    int tid = threadIdx.x;
    float s = 0.f;
#pragma unroll
    for (int i = 0; i < 4; i++) s += g_x[(size_t)tok * DM + tid + i * 256];
    __shared__ float sm[256];
    sm[tid] = s; __syncthreads();
    for (int st = 128; st > 0; st >>= 1) { if (tid < st) sm[tid] += sm[tid + st]; __syncthreads(); }
    if (tid == 0) {
        float m = (sm[0] != 0.f) ? 1.f : 0.f;
        g_mask[tok] = m;
        if (m != 0.f) atomicAdd(&g_cntb[tok / LSEQ], 1);
    }
}

__global__ void pool_k() {
    int b = blockIdx.x;
    int d = blockIdx.y * 256 + threadIdx.x;
    float acc = 0.f;
    for (int l = 0; l < LSEQ; l++)
        acc += g_x[(size_t)(b * LSEQ + l) * DM + d] * g_mask[b * LSEQ + l];
    g_pooled[b * DM + d] = acc / fmaxf((float)g_cntb[b], 1.f);
}

__global__ void head_k(const float* __restrict__ w1, const float* __restrict__ b1,
                       const float* __restrict__ w2, const float* __restrict__ b2,
                       float* __restrict__ out) {
    int b = blockIdx.x;
    int j = threadIdx.x;
    const float* p = g_pooled + b * DM;
    float acc = b1[j];
    for (int k = 0; k < DM; k++) acc += p[k] * w1[j * DM + k];
    __shared__ float h[128];
    h[j] = fmaxf(acc, 0.f);
    __syncthreads();
    if (j < 2) {
        float o = b2[j];
        for (int k = 0; k < 128; k++) o += h[k] * w2[j * 128 + k];
        out[b * 2 + j] = o;
    }
}

// ---------------- launch ----------------
extern "C" void kernel_launch(void* const* d_in, const int* in_sizes, int n_in,
                              void* d_out, int out_size) {
    const int*   tok    = (const int*)  d_in[0];
    const float* emb    = (const float*)d_in[1];
    const float* pos    = (const float*)d_in[2];
    const float* in_w   = (const float*)d_in[3];
    const float* conv_w = (const float*)d_in[4];
    const float* conv_b = (const float*)d_in[5];
    const float* xp_w   = (const float*)d_in[6];
    const float* dt_w   = (const float*)d_in[7];
    const float* dt_b   = (const float*)d_in[8];
    const float* A_log  = (const float*)d_in[9];
    const float* D_ssm  = (const float*)d_in[10];
    const float* out_w  = (const float*)d_in[11];
    const float* ln1_g  = (const float*)d_in[12];
    const float* ln1_b  = (const float*)d_in[13];
    const float* ln2_g  = (const float*)d_in[14];
    const float* ln2_b  = (const float*)d_in[15];
    const float* gate_w = (const float*)d_in[16];
    const float* gate_b = (const float*)d_in[17];
    const float* e_w1   = (const float*)d_in[18];
    const float* e_b1   = (const float*)d_in[19];
    const float* e_w2   = (const float*)d_in[20];
    const float* e_b2   = (const float*)d_in[21];
    const float* fc1_w  = (const float*)d_in[22];
    const float* fc1_b  = (const float*)d_in[23];
    const float* fc2_w  = (const float*)d_in[24];
    const float* fc2_b  = (const float*)d_in[25];
    float* out = (float*)d_out;

    cudaFuncSetAttribute(mma_gemm, cudaFuncAttributeMaxDynamicSharedMemorySize, SM_TOT);

    float *puz, *pxps, *pdt, *ppp, *pew;
    __half *pxh, *pxl, *puh, *pul, *pyh, *pyl, *phh, *phl, *pdah, *pdal;
    int *pcnt, *poff, *pperm;
    cudaGetSymbolAddress((void**)&puz,  g_uz);
    cudaGetSymbolAddress((void**)&pxps, g_xps);
    cudaGetSymbolAddress((void**)&pdt,  g_dt);
    cudaGetSymbolAddress((void**)&ppp,  g_pp);
    cudaGetSymbolAddress((void**)&pew,  g_ew);
    cudaGetSymbolAddress((void**)&pxh,  g_xh);
    cudaGetSymbolAddress((void**)&pxl,  g_xl);
    cudaGetSymbolAddress((void**)&puh,  g_uh);
    cudaGetSymbolAddress((void**)&pul,  g_ul);
    cudaGetSymbolAddress((void**)&pyh,  g_yh);
    cudaGetSymbolAddress((void**)&pyl,  g_yl);
    cudaGetSymbolAddress((void**)&phh,  g_hh);
    cudaGetSymbolAddress((void**)&phl,  g_hl);
    cudaGetSymbolAddress((void**)&pdah, g_dah);
    cudaGetSymbolAddress((void**)&pdal, g_dal);
    cudaGetSymbolAddress((void**)&pcnt, g_cnt);
    cudaGetSymbolAddress((void**)&poff, g_off);
    cudaGetSymbolAddress((void**)&pperm,g_perm);

    embed_k<<<(NTOK * DM) / 256, 256>>>(tok, emb, pos);

    for (int l = 0; l < 2; l++) {
        const float* in_w_l  = in_w  + (size_t)l * 2 * DI * DM;
        const float* xp_w_l  = xp_w  + (size_t)l * XPD * DI;
        const float* dt_w_l  = dt_w  + (size_t)l * DI * DTR;
        const float* out_w_l = out_w + (size_t)l * DM * DI;
        const float* e_w1_l  = e_w1  + (size_t)l * NEXP * HEXP * DM;
        const float* e_w2_l  = e_w2  + (size_t)l * NEXP * DM * HEXP;
        const float* A_log_l = A_log + (size_t)l * DI * DS;

        // in_proj: uz = x @ in_w^T  [4096 x 4096], K=1024, no split
        mma_gemm<<<dim3(32, 32, 1), 256, SM_TOT>>>(
            pxh, pxl, DM, in_w_l, DM, 0, puz, 2 * DI, 0, nullptr, nullptr,
            nullptr, 0, NTOK, nullptr, nullptr, nullptr, nullptr, 0, 2 * DI, DM, 32, 0);

        conv_silu_k<<<(NTOK * DI) / 256, 256>>>(conv_w + (size_t)l * DI * 4, conv_b + (size_t)l * DI);

        // xp: split-K x8 (nyb=1, grid.y=8), K=256 each
        mma_gemm<<<dim3(32, KSPL, 1), 256, SM_TOT>>>(
            puh, pul, DI, xp_w_l, DI, 0, pxps, XPD, (size_t)NTOK * XPD, nullptr, nullptr,
            nullptr, 0, NTOK, nullptr, nullptr, nullptr, nullptr, 0, XPD, DI / KSPL, 1, 0);
        xp_reduce_k<<<(NTOK * XPD) / 256, 256>>>();

        // dt = softplus(...): K=64, no split
        dtconv_k<<<(NTOK * DTR) / 256, 256>>>();
        mma_gemm<<<dim3(32, 16, 1), 256, SM_TOT>>>(
            pdah, pdal, DTR, dt_w_l, DTR, 0, pdt, DI, 0, nullptr, nullptr,
            dt_b + (size_t)l * DI, 0, NTOK, nullptr, nullptr, nullptr, nullptr, 0, DI, DTR, 16, 2);

        // segmented scan
        scan_p1<<<dim3(BATCH, DI / 128, SEG), 128>>>(A_log_l);
        scan_comb<<<dim3(BATCH, DI / 128), 128>>>(A_log_l);
        scan_p2<<<dim3(BATCH, DI / 128, SEG), 128>>>(A_log_l, D_ssm + (size_t)l * DI);

        // out: split-K x2 (nyb=8, grid.y=16), partials -> g_pp
        mma_gemm<<<dim3(32, 16, 1), 256, SM_TOT>>>(
            pyh, pyl, DI, out_w_l, DI, 0, ppp, DM, (size_t)NTOK * DM, nullptr, nullptr,
            nullptr, 0, NTOK, nullptr, nullptr, nullptr, nullptr, 0, DM, DI / 2, 8, 0);

        addln_k<<<NTOK, 256>>>(ln1_g + (size_t)l * DM, ln1_b + (size_t)l * DM,
                               ppp, ppp + (size_t)NTOK * DM);

        // MoE routing
        route_reset_k<<<1, 32>>>();
        gate_k<<<NTOK, 256>>>(gate_w + (size_t)l * NEXP * DM, gate_b + (size_t)l * NEXP);
        route_offsets_k<<<1, 1>>>();
        route_scatter_k<<<NTOK / 256, 256>>>();

        // moe1: split-K x2, fp32 partials (compact rows), then combine
        mma_gemm<<<dim3(32, 16, NEXP), 256, SM_TOT>>>(
            pxh, pxl, DM, e_w1_l, DM, (size_t)HEXP * DM, ppp, HEXP, (size_t)NTOK * HEXP,
            nullptr, nullptr, nullptr, 0, 0, pcnt, poff, pperm, nullptr, 1, HEXP, DM / 2, 8, 0);
        moe1_comb<<<(NTOK * HEXP) / 256, 256>>>(e_b1 + (size_t)l * NEXP * HEXP);

        // moe2: split-K x2, scattered+scaled partials -> g_pp
        mma_gemm<<<dim3(32, 16, NEXP), 256, SM_TOT>>>(
            phh, phl, HEXP, e_w2_l, HEXP, (size_t)DM * HEXP, ppp, DM, (size_t)NTOK * DM,
            nullptr, nullptr, e_b2 + (size_t)l * NEXP * DM, DM, 0, pcnt, poff, pperm, pew,
            2, DM, HEXP / 2, 8, 0);

        addln_k<<<NTOK, 256>>>(ln2_g + (size_t)l * DM, ln2_b + (size_t)l * DM,
                               ppp, ppp + (size_t)NTOK * DM);
    }

    cntb_reset_k<<<1, 32>>>();
    rowmask_k<<<NTOK, 256>>>();
    pool_k<<<dim3(BATCH, DM / 256), 256>>>();
    head_k<<<BATCH, 128>>>(fc1_w, fc1_b, fc2_w, fc2_b, out);
}